// round 13
// baseline (speedup 1.0000x reference)
#include <cuda_runtime.h>
#include <cuda_fp16.h>
#include <cstdint>
#include <math.h>

// Problem constants
#define BATCH   16384
#define IN_DIM  784
#define NHID    2000
#define KWIN    200
#define NCLS    10

// ---------------- device scratch ----------------
__device__ __align__(256) float  g_h  [(size_t)BATCH * NHID];
__device__ __align__(256) __half g_xhi[(size_t)BATCH * IN_DIM];
__device__ __align__(256) __half g_xlo[(size_t)BATCH * IN_DIM];
__device__ __align__(256) __half g_whi[(size_t)NHID * IN_DIM];
__device__ __align__(256) __half g_wlo[(size_t)NHID * IN_DIM];
__device__ __align__(256) float  g_w2t[(size_t)NHID * 12];
__device__ __align__(256) float  g_boost[NHID];

// ---------------- helpers ----------------
__device__ __forceinline__ uint32_t smem_u32(const void* p) {
    uint32_t a;
    asm("{ .reg .u64 t; cvta.to.shared.u64 t, %1; cvt.u32.u64 %0, t; }" : "=r"(a) : "l"(p));
    return a;
}

__device__ __forceinline__ void cpa16z(uint32_t dst, const void* src, bool valid) {
    int sz = valid ? 16 : 0;
    asm volatile("cp.async.cg.shared.global [%0], [%1], 16, %2;"
                 :: "r"(dst), "l"(src), "r"(sz));
}

__device__ __forceinline__ void ldsm_x4(uint32_t addr, uint32_t* r) {
    asm volatile("ldmatrix.sync.aligned.m8n8.x4.shared.b16 {%0,%1,%2,%3}, [%4];"
                 : "=r"(r[0]), "=r"(r[1]), "=r"(r[2]), "=r"(r[3]) : "r"(addr));
}

__device__ __forceinline__ void mma_f16(float* c, const uint32_t* a, uint32_t b0, uint32_t b1) {
    asm volatile("mma.sync.aligned.m16n8k16.row.col.f32.f16.f16.f32 "
                 "{%0,%1,%2,%3}, {%4,%5,%6,%7}, {%8,%9}, {%0,%1,%2,%3};"
                 : "+f"(c[0]), "+f"(c[1]), "+f"(c[2]), "+f"(c[3])
                 : "r"(a[0]), "r"(a[1]), "r"(a[2]), "r"(a[3]), "r"(b0), "r"(b1));
}

__device__ __forceinline__ unsigned key_xform(float v) {
    unsigned u = __float_as_uint(v);
    return (u & 0x80000000u) ? ~u : (u | 0x80000000u);
}

// ---------------- split fp32 -> (fp16 hi, fp16 lo-residual) ----------------
__global__ void split_kernel(const float* __restrict__ src,
                             __half* __restrict__ hi,
                             __half* __restrict__ lo, int n4)
{
    int i = blockIdx.x * blockDim.x + threadIdx.x;
    const int stride = gridDim.x * blockDim.x;
    for (; i < n4; i += stride) {
        float4 v = ((const float4*)src)[i];
        __half h0 = __float2half_rn(v.x);
        __half h1 = __float2half_rn(v.y);
        __half h2 = __float2half_rn(v.z);
        __half h3 = __float2half_rn(v.w);
        __half2 ha; ha.x = h0; ha.y = h1;
        __half2 hb; hb.x = h2; hb.y = h3;
        ((__half2*)hi)[2 * i]     = ha;
        ((__half2*)hi)[2 * i + 1] = hb;
        __half2 la, lb;
        la.x = __float2half_rn(v.x - __half2float(h0));
        la.y = __float2half_rn(v.y - __half2float(h1));
        lb.x = __float2half_rn(v.z - __half2float(h2));
        lb.y = __float2half_rn(v.w - __half2float(h3));
        ((__half2*)lo)[2 * i]     = la;
        ((__half2*)lo)[2 * i + 1] = lb;
    }
}

// ---------------- W2 transpose [10][2000]->[2000][12] + boost table ----------------
__global__ void w2t_kernel(const float* __restrict__ W2, const float* __restrict__ duty,
                           float* __restrict__ W2t, float* __restrict__ boost)
{
    const int i = blockIdx.x * blockDim.x + threadIdx.x;
    if (i < NHID) {
        float v[12];
        #pragma unroll
        for (int c = 0; c < NCLS; c++) v[c] = W2[c * NHID + i];
        v[10] = 0.f; v[11] = 0.f;
        float4* dst = (float4*)(W2t + (size_t)i * 12);
        dst[0] = make_float4(v[0], v[1], v[2], v[3]);
        dst[1] = make_float4(v[4], v[5], v[6], v[7]);
        dst[2] = make_float4(v[8], v[9], v[10], v[11]);
        boost[i] = expf(0.1f - duty[i]);   // boostStrength=1, targetDensity=k/n=0.1
    }
}

// ---------------- HMMA GEMM1: h = x @ W1^T + b1 (split-fp16, 3 terms) ----------------
#define BM 128
#define BN 128
#define BKG 32
#define NCHUNK 25
#define MAT_SZ (128 * 64)           // 8192 B
#define STAGE_SZ (4 * MAT_SZ)       // 32768 B
#define NSTAGE 3
#define SMEM_GEMM (NSTAGE * STAGE_SZ)   // 98304 B -> 2 CTAs/SM

__global__ __launch_bounds__(256, 2)
void gemm1_mma(const __half* __restrict__ xhi, const __half* __restrict__ xlo,
               const __half* __restrict__ whi, const __half* __restrict__ wlo,
               const float* __restrict__ bias, float* __restrict__ H)
{
    extern __shared__ __align__(1024) char smem[];
    const uint32_t sb = smem_u32(smem);
    const int tid = threadIdx.x;
    const int lane = tid & 31;
    const int wid = tid >> 5;
    const int wm = wid & 1;
    const int wn = wid >> 1;
    const int m0 = blockIdx.y * BM;
    const int n0 = blockIdx.x * BN;

    const __half* srcp[8];
    uint32_t      dsto[8];
    bool          nv[8];
    int           segl[8];
    #pragma unroll
    for (int j = 0; j < 8; j++) {
        const int mat = j >> 1;                        // 0:Ahi 1:Alo 2:Bhi 3:Blo
        const int idx = (j & 1) * 256 + tid;
        const int row = idx >> 2;
        const int seg = idx & 3;
        segl[j] = seg;
        const uint32_t sseg = (uint32_t)seg ^ (((uint32_t)row >> 1) & 3u);
        dsto[j] = (uint32_t)(mat * MAT_SZ + row * 64 + sseg * 16);
        if (mat < 2) {
            srcp[j] = (mat == 0 ? xhi : xlo) + (size_t)(m0 + row) * IN_DIM + seg * 8;
            nv[j] = true;
        } else {
            const int n = n0 + row;
            nv[j] = (n < NHID);
            const int nn = nv[j] ? n : 0;
            srcp[j] = (mat == 2 ? whi : wlo) + (size_t)nn * IN_DIM + seg * 8;
        }
    }

    auto load_chunk = [&](int c) {
        const uint32_t base = sb + (uint32_t)(c % NSTAGE) * STAGE_SZ;
        const int klim = IN_DIM - c * BKG;
        #pragma unroll
        for (int j = 0; j < 8; j++) {
            const bool valid = nv[j] && (segl[j] * 8 < klim);
            cpa16z(base + dsto[j], srcp[j] + (size_t)c * BKG, valid);
        }
        asm volatile("cp.async.commit_group;");
    };

    float acc[4][4][4];
    #pragma unroll
    for (int i = 0; i < 4; i++)
        #pragma unroll
        for (int j = 0; j < 4; j++)
            #pragma unroll
            for (int q = 0; q < 4; q++) acc[i][j][q] = 0.f;

    const uint32_t aSwz = (uint32_t)(((lane & 15) >> 1) & 3);
    const uint32_t bSwz = (uint32_t)(((lane & 7) >> 1) & 3);
    const uint32_t aChunkHi = (uint32_t)(lane >> 4);
    const uint32_t bChunkHi = (uint32_t)((lane >> 3) & 1);
    const uint32_t aRow = (uint32_t)((wm * 64 + (lane & 15)) * 64);
    const uint32_t bRow = (uint32_t)((wn * 32 + (lane >> 4) * 8 + (lane & 7)) * 64);

    load_chunk(0);
    load_chunk(1);

    for (int c = 0; c < NCHUNK; c++) {
        if (c + 1 < NCHUNK) {
            asm volatile("cp.async.wait_group 1;");
        } else {
            asm volatile("cp.async.wait_group 0;");
        }
        __syncthreads();

        if (c + 2 < NCHUNK) load_chunk(c + 2);

        const uint32_t base = sb + (uint32_t)(c % NSTAGE) * STAGE_SZ;
        #pragma unroll
        for (int kk = 0; kk < 2; kk++) {
            const uint32_t aOff = (((uint32_t)(kk * 2) + aChunkHi) ^ aSwz) * 16;
            const uint32_t bOff = (((uint32_t)(kk * 2) + bChunkHi) ^ bSwz) * 16;

            uint32_t ra[2][4][4];
            #pragma unroll
            for (int i = 0; i < 4; i++) {
                const uint32_t ao = base + aRow + (uint32_t)(i * 1024) + aOff;
                ldsm_x4(ao,          ra[0][i]);
                ldsm_x4(ao + MAT_SZ, ra[1][i]);
            }
            uint32_t rb[2][2][4];
            #pragma unroll
            for (int jj = 0; jj < 2; jj++) {
                const uint32_t bo = base + 2 * MAT_SZ + bRow + (uint32_t)(jj * 1024) + bOff;
                ldsm_x4(bo,          rb[0][jj]);
                ldsm_x4(bo + MAT_SZ, rb[1][jj]);
            }

            #pragma unroll
            for (int t = 0; t < 3; t++) {
                const int ta = (t == 2) ? 1 : 0;
                const int tb = (t == 1) ? 1 : 0;
                #pragma unroll
                for (int i = 0; i < 4; i++) {
                    #pragma unroll
                    for (int j = 0; j < 4; j++) {
                        const int jj = j >> 1;
                        const int pr = (j & 1) * 2;
                        mma_f16(acc[i][j], ra[ta][i], rb[tb][jj][pr], rb[tb][jj][pr + 1]);
                    }
                }
            }
        }
    }

    #pragma unroll
    for (int i = 0; i < 4; i++) {
        const int r0 = m0 + wm * 64 + i * 16 + (lane >> 2);
        #pragma unroll
        for (int j = 0; j < 4; j++) {
            const int col = n0 + wn * 32 + j * 8 + (lane & 3) * 2;
            if (col < NHID) {
                const float bx = __ldg(bias + col);
                const float by = __ldg(bias + col + 1);
                float2 v0 = make_float2(acc[i][j][0] + bx, acc[i][j][1] + by);
                float2 v1 = make_float2(acc[i][j][2] + bx, acc[i][j][3] + by);
                *(float2*)(H + (size_t)r0 * NHID + col)       = v0;
                *(float2*)(H + (size_t)(r0 + 8) * NHID + col) = v1;
            }
        }
    }
}

// ---------------- Kernel B: warp-per-row k-winners (tiered compaction) ----------------
#define WPC 8
#define NV4 (NHID / 4)     // 500 packed entries (4 keys16 each)
#define CCAP 64
#define WCAP 224           // winners are exactly KWIN=200
#define BCAP 512           // boundary-byte list cap (fallback if exceeded)

__global__ __launch_bounds__(256)
void kwin_head_kernel(const float* __restrict__ H,
                      const float* __restrict__ W2t,
                      const float* __restrict__ b2v,
                      const float* __restrict__ boost,
                      float* __restrict__ out)
{
    __shared__ uint2          keysS[WPC][NV4];
    __shared__ unsigned       histS[WPC][256];
    __shared__ unsigned       candKeyS[WPC][CCAP];
    __shared__ unsigned short candIdxS[WPC][CCAP];
    __shared__ unsigned short wlistS[WPC][WCAP];
    __shared__ unsigned short blistS[WPC][BCAP];

    const int lane = threadIdx.x & 31;
    const int warp = threadIdx.x >> 5;
    const int row  = blockIdx.x * WPC + warp;
    const float*  hrow = H + (size_t)row * NHID;
    const float4* h4p  = (const float4*)hrow;
    const float4* b4p  = (const float4*)boost;
    uint2*          keys2 = keysS[warp];
    unsigned*       hist  = histS[warp];
    unsigned*       ckey  = candKeyS[warp];
    unsigned short* cidx  = candIdxS[warp];
    unsigned short* wlist = wlistS[warp];
    unsigned short* blist = blistS[warp];
    const unsigned FULL = 0xFFFFFFFFu;
    const unsigned laneLT = (1u << lane) - 1u;

    auto suffix_select = [&](int K, unsigned& binOut, int& kremOut) {
        unsigned gsum[8];
        #pragma unroll
        for (int g = 0; g < 8; g++) {
            unsigned s = hist[g * 32 + lane];
            #pragma unroll
            for (int off = 16; off; off >>= 1) s += __shfl_xor_sync(FULL, s, off);
            gsum[g] = s;
        }
        int gstar = 0; unsigned above = 0; unsigned run = 0;
        #pragma unroll
        for (int g = 7; g >= 0; g--) {
            if (run < (unsigned)K && run + gsum[g] >= (unsigned)K) { gstar = g; above = run; }
            run += gsum[g];
        }
        const unsigned v = hist[gstar * 32 + lane];
        unsigned suf = v;
        #pragma unroll
        for (int off = 1; off < 32; off <<= 1) {
            const unsigned t = __shfl_down_sync(FULL, suf, off);
            if (lane + off < 32) suf += t;
        }
        const unsigned suft  = suf + above;
        const unsigned below = suft - v;
        const bool found = (suft >= (unsigned)K) && (below < (unsigned)K);
        const unsigned fm = __ballot_sync(FULL, found);
        const int src = __ffs(fm) - 1;
        binOut  = (unsigned)(gstar * 32 + src);
        kremOut = __shfl_sync(FULL, (int)((unsigned)K - below), src);
    };

    #pragma unroll
    for (int g = 0; g < 8; g++) hist[g * 32 + lane] = 0u;
    __syncwarp();

    // ---- pass 1 (global): build keys16 -> smem, top-byte histogram ----
    for (int v0 = 0; v0 < NV4; v0 += 32) {
        const int v = v0 + lane;
        const bool in = v < NV4;
        const unsigned act = __ballot_sync(FULL, in);
        if (in) {
            const float4 h4 = h4p[v];
            const float4 b4 = b4p[v];
            unsigned k16[4];
            k16[0] = key_xform(h4.x * b4.x) >> 16;
            k16[1] = key_xform(h4.y * b4.y) >> 16;
            k16[2] = key_xform(h4.z * b4.z) >> 16;
            k16[3] = key_xform(h4.w * b4.w) >> 16;
            keys2[v] = make_uint2(k16[0] | (k16[1] << 16), k16[2] | (k16[3] << 16));
            #pragma unroll
            for (int q = 0; q < 4; q++) {
                const unsigned bin = k16[q] >> 8;
                const unsigned mm = __match_any_sync(act, bin);
                if (__ffs(mm) - 1 == lane)
                    atomicAdd(&hist[bin], (unsigned)__popc(mm));
            }
        }
    }
    __syncwarp();

    unsigned b1; int k1;
    suffix_select(KWIN, b1, k1);

    #pragma unroll
    for (int g = 0; g < 8; g++) hist[g * 32 + lane] = 0u;
    __syncwarp();

    // ---- pass 2 (smem): ONE sweep -> byte-strict winners to wlist,
    //      boundary-byte elems to blist, low-byte histogram of boundary elems ----
    int wcnt = 0, bcnt = 0;
    for (int v0 = 0; v0 < NV4; v0 += 32) {
        const int v = v0 + lane;
        const bool in = v < NV4;
        unsigned k16[4];
        bool sw[4], bq[4];
        unsigned nw = 0, nb = 0;
        if (in) {
            const uint2 kk = keys2[v];
            k16[0] = kk.x & 0xFFFFu; k16[1] = kk.x >> 16;
            k16[2] = kk.y & 0xFFFFu; k16[3] = kk.y >> 16;
            #pragma unroll
            for (int q = 0; q < 4; q++) {
                const unsigned by = k16[q] >> 8;
                sw[q] = (by > b1);
                bq[q] = (by == b1);
                nw += sw[q]; nb += bq[q];
            }
        } else {
            #pragma unroll
            for (int q = 0; q < 4; q++) { sw[q] = false; bq[q] = false; }
        }
        // packed exclusive scan (nb<<16 | nw)
        unsigned pk = (nb << 16) | nw;
        unsigned sc = pk;
        #pragma unroll
        for (int off = 1; off < 32; off <<= 1) {
            const unsigned t = __shfl_up_sync(FULL, sc, off);
            if (lane >= off) sc += t;
        }
        const unsigned tot = __shfl_sync(FULL, sc, 31);
        const unsigned exc = sc - pk;
        int wpos = wcnt + (int)(exc & 0xFFFFu);
        int bpos = bcnt + (int)(exc >> 16);
        if (in) {
            #pragma unroll
            for (int q = 0; q < 4; q++) {
                if (sw[q]) {
                    if (wpos < WCAP) wlist[wpos] = (unsigned short)(v * 4 + q);
                    wpos++;
                }
                if (bq[q]) {
                    if (bpos < BCAP) blist[bpos] = (unsigned short)(v * 4 + q);
                    bpos++;
                    atomicAdd(&hist[k16[q] & 255u], 1u);
                }
            }
        }
        wcnt += (int)(tot & 0xFFFFu);
        bcnt += (int)(tot >> 16);
    }
    __syncwarp();

    unsigned b2bin; int k2;
    suffix_select(k1, b2bin, k2);
    const unsigned thr16 = (b1 << 8) | b2bin;

    int Wn = wcnt;          // byte-strict winners (always < KWIN <= WCAP)
    int ccnt = 0;

    // ---- pass 3: scan boundary list (or full fallback) for low-byte winners + candidates ----
    if (bcnt <= BCAP) {
        for (int j0 = 0; j0 < bcnt; j0 += 32) {
            const int j = j0 + lane;
            const bool in = j < bcnt;
            int ii = 0; unsigned low = 0;
            if (in) {
                ii = blist[j];
                const uint2 kk = keys2[ii >> 2];
                const unsigned word = (ii & 2) ? kk.y : kk.x;
                const unsigned k16v = (ii & 1) ? (word >> 16) : (word & 0xFFFFu);
                low = k16v & 255u;
            }
            const bool w2 = in && (low > b2bin);
            const bool cq = in && (low == b2bin);
            const unsigned wmk = __ballot_sync(FULL, w2);
            if (w2) wlist[Wn + __popc(wmk & laneLT)] = (unsigned short)ii;
            Wn += __popc(wmk);
            const unsigned cmk = __ballot_sync(FULL, cq);
            if (cq) {
                const int pos = ccnt + __popc(cmk & laneLT);
                if (pos < CCAP) cidx[pos] = (unsigned short)ii;
            }
            ccnt += __popc(cmk);
        }
    } else {
        // fallback: full scan (rare)
        for (int v0 = 0; v0 < NV4; v0 += 32) {
            const int v = v0 + lane;
            const bool in = v < NV4;
            unsigned k16[4]; bool w2[4], cq[4];
            if (in) {
                const uint2 kk = keys2[v];
                k16[0] = kk.x & 0xFFFFu; k16[1] = kk.x >> 16;
                k16[2] = kk.y & 0xFFFFu; k16[3] = kk.y >> 16;
                #pragma unroll
                for (int q = 0; q < 4; q++) {
                    w2[q] = ((k16[q] >> 8) == b1) && ((k16[q] & 255u) > b2bin);
                    cq[q] = (k16[q] == thr16);
                }
            } else {
                #pragma unroll
                for (int q = 0; q < 4; q++) { w2[q] = false; cq[q] = false; }
            }
            #pragma unroll
            for (int q = 0; q < 4; q++) {
                const unsigned wmk = __ballot_sync(FULL, w2[q]);
                if (w2[q]) wlist[Wn + __popc(wmk & laneLT)] = (unsigned short)(v * 4 + q);
                Wn += __popc(wmk);
                const unsigned cmk = __ballot_sync(FULL, cq[q]);
                if (cq[q]) {
                    const int pos = ccnt + __popc(cmk & laneLT);
                    if (pos < CCAP) cidx[pos] = (unsigned short)(v * 4 + q);
                }
                ccnt += __popc(cmk);
            }
        }
    }
    __syncwarp();
    const int L = (ccnt < CCAP) ? ccnt : CCAP;

    // boundary candidates: full keys, exact rank (key desc, idx asc), append top-k2
    for (int j = lane; j < L; j += 32) {
        const int ii = cidx[j];
        ckey[j] = key_xform(__ldg(&hrow[ii]) * __ldg(&boost[ii]));
    }
    __syncwarp();
    for (int j0 = 0; j0 < L; j0 += 32) {
        const int j = j0 + lane;
        bool win = false;
        int ii = 0;
        if (j < L) {
            const unsigned ku = ckey[j];
            ii = cidx[j];
            int rank = 0;
            for (int t = 0; t < L; t++) {
                const unsigned kt = ckey[t];
                rank += (kt > ku) || (kt == ku && (int)cidx[t] < ii);
            }
            win = (rank < k2);
        }
        const unsigned mask = __ballot_sync(FULL, win);
        if (win) wlist[Wn + __popc(mask & laneLT)] = (unsigned short)ii;
        Wn += __popc(mask);
    }
    __syncwarp();
    if (Wn > WCAP) Wn = WCAP;

    // ---- pass 4: dense accumulation over compacted winner list ----
    float acc[NCLS];
    #pragma unroll
    for (int c = 0; c < NCLS; c++) acc[c] = 0.f;

    for (int j = lane; j < Wn; j += 32) {
        const int i = wlist[j];
        const float hv = __ldg(&hrow[i]);
        const float4* wp = (const float4*)(W2t + (size_t)i * 12);
        const float4 w0 = __ldg(wp);
        const float4 w1 = __ldg(wp + 1);
        const float4 w2 = __ldg(wp + 2);
        acc[0] = fmaf(hv, w0.x, acc[0]);
        acc[1] = fmaf(hv, w0.y, acc[1]);
        acc[2] = fmaf(hv, w0.z, acc[2]);
        acc[3] = fmaf(hv, w0.w, acc[3]);
        acc[4] = fmaf(hv, w1.x, acc[4]);
        acc[5] = fmaf(hv, w1.y, acc[5]);
        acc[6] = fmaf(hv, w1.z, acc[6]);
        acc[7] = fmaf(hv, w1.w, acc[7]);
        acc[8] = fmaf(hv, w2.x, acc[8]);
        acc[9] = fmaf(hv, w2.y, acc[9]);
    }

    #pragma unroll
    for (int off = 16; off; off >>= 1)
        #pragma unroll
        for (int c = 0; c < NCLS; c++)
            acc[c] += __shfl_xor_sync(FULL, acc[c], off);

    if (lane == 0) {
        float lg[NCLS];
        #pragma unroll
        for (int c = 0; c < NCLS; c++) lg[c] = acc[c] + __ldg(&b2v[c]);
        float mx = lg[0];
        #pragma unroll
        for (int c = 1; c < NCLS; c++) mx = fmaxf(mx, lg[c]);
        float se = 0.f;
        #pragma unroll
        for (int c = 0; c < NCLS; c++) se += expf(lg[c] - mx);
        const float lse = mx + logf(se);
        float* orow = out + (size_t)row * NCLS;
        #pragma unroll
        for (int c = 0; c < NCLS; c++) orow[c] = lg[c] - lse;
    }
}

// ---------------- launch ----------------
extern "C" void kernel_launch(void* const* d_in, const int* in_sizes, int n_in,
                              void* d_out, int out_size)
{
    const float* x    = (const float*)d_in[0];   // [16384, 784]
    const float* W1   = (const float*)d_in[1];   // [2000, 784]
    const float* b1   = (const float*)d_in[2];   // [2000]
    const float* W2   = (const float*)d_in[3];   // [10, 2000]
    const float* b2   = (const float*)d_in[4];   // [10]
    const float* duty = (const float*)d_in[5];   // [2000]
    float* out = (float*)d_out;                  // [16384, 10]

    float*  h;    cudaGetSymbolAddress((void**)&h,   g_h);
    __half* xhi;  cudaGetSymbolAddress((void**)&xhi, g_xhi);
    __half* xlo;  cudaGetSymbolAddress((void**)&xlo, g_xlo);
    __half* whi;  cudaGetSymbolAddress((void**)&whi, g_whi);
    __half* wlo;  cudaGetSymbolAddress((void**)&wlo, g_wlo);
    float*  w2t;  cudaGetSymbolAddress((void**)&w2t, g_w2t);
    float*  bst;  cudaGetSymbolAddress((void**)&bst, g_boost);

    split_kernel<<<1024, 256>>>(x,  xhi, xlo, (BATCH * IN_DIM) / 4);
    split_kernel<<<512,  256>>>(W1, whi, wlo, (NHID  * IN_DIM) / 4);
    w2t_kernel<<<(NHID + 255) / 256, 256>>>(W2, duty, w2t, bst);

    cudaFuncSetAttribute(gemm1_mma, cudaFuncAttributeMaxDynamicSharedMemorySize, SMEM_GEMM);
    dim3 gridG((NHID + BN - 1) / BN, BATCH / BM);   // (16, 128)
    gemm1_mma<<<gridG, 256, SMEM_GEMM>>>(xhi, xlo, whi, wlo, b1, h);

    kwin_head_kernel<<<BATCH / WPC, 256>>>(h, w2t, b2, bst, out);
}

// round 14
// speedup vs baseline: 1.0309x; 1.0309x over previous
#include <cuda_runtime.h>
#include <cuda_fp16.h>
#include <cstdint>
#include <math.h>

// Problem constants
#define BATCH   16384
#define IN_DIM  784
#define NHID    2000
#define KWIN    200
#define NCLS    10

// ---------------- device scratch ----------------
__device__ __align__(256) float          g_h  [(size_t)BATCH * NHID];
__device__ __align__(256) unsigned short g_k16[(size_t)BATCH * NHID];   // top-16 bits of boosted keys
__device__ __align__(256) __half g_xhi[(size_t)BATCH * IN_DIM];
__device__ __align__(256) __half g_xlo[(size_t)BATCH * IN_DIM];
__device__ __align__(256) __half g_whi[(size_t)NHID * IN_DIM];
__device__ __align__(256) __half g_wlo[(size_t)NHID * IN_DIM];
__device__ __align__(256) float  g_w2t[(size_t)NHID * 12];
__device__ __align__(256) float  g_boost[NHID];

// ---------------- helpers ----------------
__device__ __forceinline__ uint32_t smem_u32(const void* p) {
    uint32_t a;
    asm("{ .reg .u64 t; cvta.to.shared.u64 t, %1; cvt.u32.u64 %0, t; }" : "=r"(a) : "l"(p));
    return a;
}

__device__ __forceinline__ void cpa16z(uint32_t dst, const void* src, bool valid) {
    int sz = valid ? 16 : 0;
    asm volatile("cp.async.cg.shared.global [%0], [%1], 16, %2;"
                 :: "r"(dst), "l"(src), "r"(sz));
}

__device__ __forceinline__ void ldsm_x4(uint32_t addr, uint32_t* r) {
    asm volatile("ldmatrix.sync.aligned.m8n8.x4.shared.b16 {%0,%1,%2,%3}, [%4];"
                 : "=r"(r[0]), "=r"(r[1]), "=r"(r[2]), "=r"(r[3]) : "r"(addr));
}

__device__ __forceinline__ void mma_f16(float* c, const uint32_t* a, uint32_t b0, uint32_t b1) {
    asm volatile("mma.sync.aligned.m16n8k16.row.col.f32.f16.f16.f32 "
                 "{%0,%1,%2,%3}, {%4,%5,%6,%7}, {%8,%9}, {%0,%1,%2,%3};"
                 : "+f"(c[0]), "+f"(c[1]), "+f"(c[2]), "+f"(c[3])
                 : "r"(a[0]), "r"(a[1]), "r"(a[2]), "r"(a[3]), "r"(b0), "r"(b1));
}

__device__ __forceinline__ unsigned key_xform(float v) {
    unsigned u = __float_as_uint(v);
    return (u & 0x80000000u) ? ~u : (u | 0x80000000u);
}

// ---------------- split fp32 -> (fp16 hi, fp16 lo-residual) ----------------
__global__ void split_kernel(const float* __restrict__ src,
                             __half* __restrict__ hi,
                             __half* __restrict__ lo, int n4)
{
    int i = blockIdx.x * blockDim.x + threadIdx.x;
    const int stride = gridDim.x * blockDim.x;
    for (; i < n4; i += stride) {
        float4 v = ((const float4*)src)[i];
        __half h0 = __float2half_rn(v.x);
        __half h1 = __float2half_rn(v.y);
        __half h2 = __float2half_rn(v.z);
        __half h3 = __float2half_rn(v.w);
        __half2 ha; ha.x = h0; ha.y = h1;
        __half2 hb; hb.x = h2; hb.y = h3;
        ((__half2*)hi)[2 * i]     = ha;
        ((__half2*)hi)[2 * i + 1] = hb;
        __half2 la, lb;
        la.x = __float2half_rn(v.x - __half2float(h0));
        la.y = __float2half_rn(v.y - __half2float(h1));
        lb.x = __float2half_rn(v.z - __half2float(h2));
        lb.y = __float2half_rn(v.w - __half2float(h3));
        ((__half2*)lo)[2 * i]     = la;
        ((__half2*)lo)[2 * i + 1] = lb;
    }
}

// ---------------- W2 transpose [10][2000]->[2000][12] + boost table ----------------
__global__ void w2t_kernel(const float* __restrict__ W2, const float* __restrict__ duty,
                           float* __restrict__ W2t, float* __restrict__ boost)
{
    const int i = blockIdx.x * blockDim.x + threadIdx.x;
    if (i < NHID) {
        float v[12];
        #pragma unroll
        for (int c = 0; c < NCLS; c++) v[c] = W2[c * NHID + i];
        v[10] = 0.f; v[11] = 0.f;
        float4* dst = (float4*)(W2t + (size_t)i * 12);
        dst[0] = make_float4(v[0], v[1], v[2], v[3]);
        dst[1] = make_float4(v[4], v[5], v[6], v[7]);
        dst[2] = make_float4(v[8], v[9], v[10], v[11]);
        boost[i] = expf(0.1f - duty[i]);   // boostStrength=1, targetDensity=k/n=0.1
    }
}

// ---------------- HMMA GEMM1: h = x @ W1^T + b1 (split-fp16, 3 terms) ----------------
// Epilogue also emits packed keys16 = key_xform(h * boost) >> 16.
#define BM 128
#define BN 128
#define BKG 32
#define NCHUNK 25
#define MAT_SZ (128 * 64)           // 8192 B
#define STAGE_SZ (4 * MAT_SZ)       // 32768 B
#define NSTAGE 3
#define SMEM_GEMM (NSTAGE * STAGE_SZ)   // 98304 B -> 2 CTAs/SM

__global__ __launch_bounds__(256, 2)
void gemm1_mma(const __half* __restrict__ xhi, const __half* __restrict__ xlo,
               const __half* __restrict__ whi, const __half* __restrict__ wlo,
               const float* __restrict__ bias, const float* __restrict__ boost,
               float* __restrict__ H, unsigned short* __restrict__ K16)
{
    extern __shared__ __align__(1024) char smem[];
    const uint32_t sb = smem_u32(smem);
    const int tid = threadIdx.x;
    const int lane = tid & 31;
    const int wid = tid >> 5;
    const int wm = wid & 1;
    const int wn = wid >> 1;
    const int m0 = blockIdx.y * BM;
    const int n0 = blockIdx.x * BN;

    const __half* srcp[8];
    uint32_t      dsto[8];
    bool          nv[8];
    int           segl[8];
    #pragma unroll
    for (int j = 0; j < 8; j++) {
        const int mat = j >> 1;                        // 0:Ahi 1:Alo 2:Bhi 3:Blo
        const int idx = (j & 1) * 256 + tid;
        const int row = idx >> 2;
        const int seg = idx & 3;
        segl[j] = seg;
        const uint32_t sseg = (uint32_t)seg ^ (((uint32_t)row >> 1) & 3u);
        dsto[j] = (uint32_t)(mat * MAT_SZ + row * 64 + sseg * 16);
        if (mat < 2) {
            srcp[j] = (mat == 0 ? xhi : xlo) + (size_t)(m0 + row) * IN_DIM + seg * 8;
            nv[j] = true;
        } else {
            const int n = n0 + row;
            nv[j] = (n < NHID);
            const int nn = nv[j] ? n : 0;
            srcp[j] = (mat == 2 ? whi : wlo) + (size_t)nn * IN_DIM + seg * 8;
        }
    }

    auto load_chunk = [&](int c) {
        const uint32_t base = sb + (uint32_t)(c % NSTAGE) * STAGE_SZ;
        const int klim = IN_DIM - c * BKG;
        #pragma unroll
        for (int j = 0; j < 8; j++) {
            const bool valid = nv[j] && (segl[j] * 8 < klim);
            cpa16z(base + dsto[j], srcp[j] + (size_t)c * BKG, valid);
        }
        asm volatile("cp.async.commit_group;");
    };

    float acc[4][4][4];
    #pragma unroll
    for (int i = 0; i < 4; i++)
        #pragma unroll
        for (int j = 0; j < 4; j++)
            #pragma unroll
            for (int q = 0; q < 4; q++) acc[i][j][q] = 0.f;

    const uint32_t aSwz = (uint32_t)(((lane & 15) >> 1) & 3);
    const uint32_t bSwz = (uint32_t)(((lane & 7) >> 1) & 3);
    const uint32_t aChunkHi = (uint32_t)(lane >> 4);
    const uint32_t bChunkHi = (uint32_t)((lane >> 3) & 1);
    const uint32_t aRow = (uint32_t)((wm * 64 + (lane & 15)) * 64);
    const uint32_t bRow = (uint32_t)((wn * 32 + (lane >> 4) * 8 + (lane & 7)) * 64);

    load_chunk(0);
    load_chunk(1);

    for (int c = 0; c < NCHUNK; c++) {
        if (c + 1 < NCHUNK) {
            asm volatile("cp.async.wait_group 1;");
        } else {
            asm volatile("cp.async.wait_group 0;");
        }
        __syncthreads();

        if (c + 2 < NCHUNK) load_chunk(c + 2);

        const uint32_t base = sb + (uint32_t)(c % NSTAGE) * STAGE_SZ;
        #pragma unroll
        for (int kk = 0; kk < 2; kk++) {
            const uint32_t aOff = (((uint32_t)(kk * 2) + aChunkHi) ^ aSwz) * 16;
            const uint32_t bOff = (((uint32_t)(kk * 2) + bChunkHi) ^ bSwz) * 16;

            uint32_t ra[2][4][4];
            #pragma unroll
            for (int i = 0; i < 4; i++) {
                const uint32_t ao = base + aRow + (uint32_t)(i * 1024) + aOff;
                ldsm_x4(ao,          ra[0][i]);
                ldsm_x4(ao + MAT_SZ, ra[1][i]);
            }
            uint32_t rb[2][2][4];
            #pragma unroll
            for (int jj = 0; jj < 2; jj++) {
                const uint32_t bo = base + 2 * MAT_SZ + bRow + (uint32_t)(jj * 1024) + bOff;
                ldsm_x4(bo,          rb[0][jj]);
                ldsm_x4(bo + MAT_SZ, rb[1][jj]);
            }

            #pragma unroll
            for (int t = 0; t < 3; t++) {
                const int ta = (t == 2) ? 1 : 0;
                const int tb = (t == 1) ? 1 : 0;
                #pragma unroll
                for (int i = 0; i < 4; i++) {
                    #pragma unroll
                    for (int j = 0; j < 4; j++) {
                        const int jj = j >> 1;
                        const int pr = (j & 1) * 2;
                        mma_f16(acc[i][j], ra[ta][i], rb[tb][jj][pr], rb[tb][jj][pr + 1]);
                    }
                }
            }
        }
    }

    // epilogue: bias + store h + store packed keys16
    #pragma unroll
    for (int i = 0; i < 4; i++) {
        const int r0 = m0 + wm * 64 + i * 16 + (lane >> 2);
        #pragma unroll
        for (int j = 0; j < 4; j++) {
            const int col = n0 + wn * 32 + j * 8 + (lane & 3) * 2;
            if (col < NHID) {
                const float bx = __ldg(bias + col);
                const float by = __ldg(bias + col + 1);
                const float sx = __ldg(boost + col);
                const float sy = __ldg(boost + col + 1);
                float2 v0 = make_float2(acc[i][j][0] + bx, acc[i][j][1] + by);
                float2 v1 = make_float2(acc[i][j][2] + bx, acc[i][j][3] + by);
                *(float2*)(H + (size_t)r0 * NHID + col)       = v0;
                *(float2*)(H + (size_t)(r0 + 8) * NHID + col) = v1;
                const unsigned ka = (key_xform(v0.x * sx) >> 16)
                                  | ((key_xform(v0.y * sy) >> 16) << 16);
                const unsigned kb = (key_xform(v1.x * sx) >> 16)
                                  | ((key_xform(v1.y * sy) >> 16) << 16);
                *(unsigned*)(K16 + (size_t)r0 * NHID + col)       = ka;
                *(unsigned*)(K16 + (size_t)(r0 + 8) * NHID + col) = kb;
            }
        }
    }
}

// ---------------- Kernel B: warp-per-row k-winners (round-12 structure, keys from gmem) ----------------
#define WPC 8
#define NV4 (NHID / 4)     // 500 packed entries (4 keys16 each)
#define CCAP 64
#define WCAP 288

__global__ __launch_bounds__(256)
void kwin_head_kernel(const float* __restrict__ H,
                      const unsigned short* __restrict__ K16,
                      const float* __restrict__ W2t,
                      const float* __restrict__ b2v,
                      const float* __restrict__ boost,
                      float* __restrict__ out)
{
    __shared__ uint2          keysS[WPC][NV4];
    __shared__ unsigned       histS[WPC][256];
    __shared__ unsigned       candKeyS[WPC][CCAP];
    __shared__ unsigned short candIdxS[WPC][CCAP];
    __shared__ unsigned short wlistS[WPC][WCAP];

    const int lane = threadIdx.x & 31;
    const int warp = threadIdx.x >> 5;
    const int row  = blockIdx.x * WPC + warp;
    const float* hrow = H + (size_t)row * NHID;
    const uint2* k4p  = (const uint2*)(K16 + (size_t)row * NHID);
    uint2*          keys2 = keysS[warp];
    unsigned*       hist  = histS[warp];
    unsigned*       ckey  = candKeyS[warp];
    unsigned short* cidx  = candIdxS[warp];
    unsigned short* wlist = wlistS[warp];
    const unsigned FULL = 0xFFFFFFFFu;
    const unsigned laneLT = (1u << lane) - 1u;

    auto suffix_select = [&](int K, unsigned& binOut, int& kremOut) {
        unsigned gsum[8];
        #pragma unroll
        for (int g = 0; g < 8; g++) {
            unsigned s = hist[g * 32 + lane];
            #pragma unroll
            for (int off = 16; off; off >>= 1) s += __shfl_xor_sync(FULL, s, off);
            gsum[g] = s;
        }
        int gstar = 0; unsigned above = 0; unsigned run = 0;
        #pragma unroll
        for (int g = 7; g >= 0; g--) {
            if (run < (unsigned)K && run + gsum[g] >= (unsigned)K) { gstar = g; above = run; }
            run += gsum[g];
        }
        const unsigned v = hist[gstar * 32 + lane];
        unsigned suf = v;
        #pragma unroll
        for (int off = 1; off < 32; off <<= 1) {
            const unsigned t = __shfl_down_sync(FULL, suf, off);
            if (lane + off < 32) suf += t;
        }
        const unsigned suft  = suf + above;
        const unsigned below = suft - v;
        const bool found = (suft >= (unsigned)K) && (below < (unsigned)K);
        const unsigned fm = __ballot_sync(FULL, found);
        const int src = __ffs(fm) - 1;
        binOut  = (unsigned)(gstar * 32 + src);
        kremOut = __shfl_sync(FULL, (int)((unsigned)K - below), src);
    };

    #pragma unroll
    for (int g = 0; g < 8; g++) hist[g * 32 + lane] = 0u;
    __syncwarp();

    // ---- pass 1: load precomputed keys16 (coalesced uint2), stash to smem, histogram ----
    for (int v0 = 0; v0 < NV4; v0 += 32) {
        const int v = v0 + lane;
        const bool in = v < NV4;
        const unsigned act = __ballot_sync(FULL, in);
        if (in) {
            const uint2 kk = __ldg(&k4p[v]);
            keys2[v] = kk;
            const unsigned k16[4] = {kk.x & 0xFFFFu, kk.x >> 16, kk.y & 0xFFFFu, kk.y >> 16};
            #pragma unroll
            for (int q = 0; q < 4; q++) {
                const unsigned bin = k16[q] >> 8;
                const unsigned mm = __match_any_sync(act, bin);
                if (__ffs(mm) - 1 == lane)
                    atomicAdd(&hist[bin], (unsigned)__popc(mm));
            }
        }
    }
    __syncwarp();

    unsigned b1; int k1;
    suffix_select(KWIN, b1, k1);

    #pragma unroll
    for (int g = 0; g < 8; g++) hist[g * 32 + lane] = 0u;
    __syncwarp();

    // ---- pass 2 (smem): low-byte histogram among top-byte == b1 ----
    for (int v0 = 0; v0 < NV4; v0 += 32) {
        const int v = v0 + lane;
        if (v < NV4) {
            const uint2 kk = keys2[v];
            const unsigned k16[4] = {kk.x & 0xFFFFu, kk.x >> 16, kk.y & 0xFFFFu, kk.y >> 16};
            #pragma unroll
            for (int q = 0; q < 4; q++)
                if ((k16[q] >> 8) == b1) atomicAdd(&hist[k16[q] & 255u], 1u);
        }
    }
    __syncwarp();

    unsigned b2bin; int k2;
    suffix_select(k1, b2bin, k2);
    const unsigned thr16 = (b1 << 8) | b2bin;

    // ---- pass 3 (smem): compact strict winners AND boundary candidates ----
    int wcnt = 0;
    int ccnt = 0;
    for (int v0 = 0; v0 < NV4; v0 += 32) {
        const int v = v0 + lane;
        const bool in = v < NV4;
        unsigned k16[4]; bool sw[4], bq[4];
        if (in) {
            const uint2 kk = keys2[v];
            k16[0] = kk.x & 0xFFFFu; k16[1] = kk.x >> 16;
            k16[2] = kk.y & 0xFFFFu; k16[3] = kk.y >> 16;
            #pragma unroll
            for (int q = 0; q < 4; q++) {
                sw[q] = (k16[q] > thr16);
                bq[q] = (k16[q] == thr16);
            }
        } else {
            #pragma unroll
            for (int q = 0; q < 4; q++) { sw[q] = false; bq[q] = false; }
        }
        #pragma unroll
        for (int q = 0; q < 4; q++) {
            const unsigned wm_ = __ballot_sync(FULL, sw[q]);
            if (sw[q]) {
                const int pos = wcnt + __popc(wm_ & laneLT);
                if (pos < WCAP) wlist[pos] = (unsigned short)(v * 4 + q);
            }
            wcnt += __popc(wm_);
            const unsigned bm_ = __ballot_sync(FULL, bq[q]);
            if (bq[q]) {
                const int pos = ccnt + __popc(bm_ & laneLT);
                if (pos < CCAP) cidx[pos] = (unsigned short)(v * 4 + q);
            }
            ccnt += __popc(bm_);
        }
    }
    __syncwarp();
    const int L = (ccnt < CCAP) ? ccnt : CCAP;
    int Wn = (wcnt < WCAP) ? wcnt : WCAP;

    // boundary candidates: full keys, exact rank (key desc, idx asc), append winners
    for (int j = lane; j < L; j += 32) {
        const int ii = cidx[j];
        ckey[j] = key_xform(__ldg(&hrow[ii]) * __ldg(&boost[ii]));
    }
    __syncwarp();
    for (int j0 = 0; j0 < L; j0 += 32) {
        const int j = j0 + lane;
        bool win = false;
        int ii = 0;
        if (j < L) {
            const unsigned ku = ckey[j];
            ii = cidx[j];
            int rank = 0;
            for (int t = 0; t < L; t++) {
                const unsigned kt = ckey[t];
                rank += (kt > ku) || (kt == ku && (int)cidx[t] < ii);
            }
            win = (rank < k2);
        }
        const unsigned mask = __ballot_sync(FULL, win);
        if (win) {
            const int pos = Wn + __popc(mask & laneLT);
            if (pos < WCAP) wlist[pos] = (unsigned short)ii;
        }
        Wn += __popc(mask);
    }
    __syncwarp();
    if (Wn > WCAP) Wn = WCAP;

    // ---- pass 4: dense accumulation over compacted winner list ----
    float acc[NCLS];
    #pragma unroll
    for (int c = 0; c < NCLS; c++) acc[c] = 0.f;

    for (int j = lane; j < Wn; j += 32) {
        const int i = wlist[j];
        const float hv = __ldg(&hrow[i]);
        const float4* wp = (const float4*)(W2t + (size_t)i * 12);
        const float4 w0 = __ldg(wp);
        const float4 w1 = __ldg(wp + 1);
        const float4 w2 = __ldg(wp + 2);
        acc[0] = fmaf(hv, w0.x, acc[0]);
        acc[1] = fmaf(hv, w0.y, acc[1]);
        acc[2] = fmaf(hv, w0.z, acc[2]);
        acc[3] = fmaf(hv, w0.w, acc[3]);
        acc[4] = fmaf(hv, w1.x, acc[4]);
        acc[5] = fmaf(hv, w1.y, acc[5]);
        acc[6] = fmaf(hv, w1.z, acc[6]);
        acc[7] = fmaf(hv, w1.w, acc[7]);
        acc[8] = fmaf(hv, w2.x, acc[8]);
        acc[9] = fmaf(hv, w2.y, acc[9]);
    }

    #pragma unroll
    for (int off = 16; off; off >>= 1)
        #pragma unroll
        for (int c = 0; c < NCLS; c++)
            acc[c] += __shfl_xor_sync(FULL, acc[c], off);

    if (lane == 0) {
        float lg[NCLS];
        #pragma unroll
        for (int c = 0; c < NCLS; c++) lg[c] = acc[c] + __ldg(&b2v[c]);
        float mx = lg[0];
        #pragma unroll
        for (int c = 1; c < NCLS; c++) mx = fmaxf(mx, lg[c]);
        float se = 0.f;
        #pragma unroll
        for (int c = 0; c < NCLS; c++) se += expf(lg[c] - mx);
        const float lse = mx + logf(se);
        float* orow = out + (size_t)row * NCLS;
        #pragma unroll
        for (int c = 0; c < NCLS; c++) orow[c] = lg[c] - lse;
    }
}

// ---------------- launch ----------------
extern "C" void kernel_launch(void* const* d_in, const int* in_sizes, int n_in,
                              void* d_out, int out_size)
{
    const float* x    = (const float*)d_in[0];   // [16384, 784]
    const float* W1   = (const float*)d_in[1];   // [2000, 784]
    const float* b1   = (const float*)d_in[2];   // [2000]
    const float* W2   = (const float*)d_in[3];   // [10, 2000]
    const float* b2   = (const float*)d_in[4];   // [10]
    const float* duty = (const float*)d_in[5];   // [2000]
    float* out = (float*)d_out;                  // [16384, 10]

    float*  h;    cudaGetSymbolAddress((void**)&h,   g_h);
    unsigned short* k16; cudaGetSymbolAddress((void**)&k16, g_k16);
    __half* xhi;  cudaGetSymbolAddress((void**)&xhi, g_xhi);
    __half* xlo;  cudaGetSymbolAddress((void**)&xlo, g_xlo);
    __half* whi;  cudaGetSymbolAddress((void**)&whi, g_whi);
    __half* wlo;  cudaGetSymbolAddress((void**)&wlo, g_wlo);
    float*  w2t;  cudaGetSymbolAddress((void**)&w2t, g_w2t);
    float*  bst;  cudaGetSymbolAddress((void**)&bst, g_boost);

    split_kernel<<<1024, 256>>>(x,  xhi, xlo, (BATCH * IN_DIM) / 4);
    split_kernel<<<512,  256>>>(W1, whi, wlo, (NHID  * IN_DIM) / 4);
    w2t_kernel<<<(NHID + 255) / 256, 256>>>(W2, duty, w2t, bst);   // boost before gemm

    cudaFuncSetAttribute(gemm1_mma, cudaFuncAttributeMaxDynamicSharedMemorySize, SMEM_GEMM);
    dim3 gridG((NHID + BN - 1) / BN, BATCH / BM);   // (16, 128)
    gemm1_mma<<<gridG, 256, SMEM_GEMM>>>(xhi, xlo, whi, wlo, b1, bst, h, k16);

    kwin_head_kernel<<<BATCH / WPC, 256>>>(h, k16, w2t, b2, bst, out);
}

// round 15
// speedup vs baseline: 1.1317x; 1.0978x over previous
#include <cuda_runtime.h>
#include <cuda_fp16.h>
#include <cstdint>
#include <math.h>

// Problem constants
#define BATCH   16384
#define IN_DIM  784
#define NHID    2000
#define KWIN    200
#define NCLS    10

// ---------------- device scratch ----------------
__device__ __align__(256) float  g_h  [(size_t)BATCH * NHID];
__device__ __align__(256) __half g_xhi[(size_t)BATCH * IN_DIM];
__device__ __align__(256) __half g_xlo[(size_t)BATCH * IN_DIM];
__device__ __align__(256) __half g_whi[(size_t)NHID * IN_DIM];
__device__ __align__(256) __half g_wlo[(size_t)NHID * IN_DIM];
__device__ __align__(256) float  g_w2t[(size_t)NHID * 12];
__device__ __align__(256) float  g_boost[NHID];

// ---------------- helpers ----------------
__device__ __forceinline__ uint32_t smem_u32(const void* p) {
    uint32_t a;
    asm("{ .reg .u64 t; cvta.to.shared.u64 t, %1; cvt.u32.u64 %0, t; }" : "=r"(a) : "l"(p));
    return a;
}

__device__ __forceinline__ void cpa16z(uint32_t dst, const void* src, bool valid) {
    int sz = valid ? 16 : 0;
    asm volatile("cp.async.cg.shared.global [%0], [%1], 16, %2;"
                 :: "r"(dst), "l"(src), "r"(sz));
}

__device__ __forceinline__ void ldsm_x4(uint32_t addr, uint32_t* r) {
    asm volatile("ldmatrix.sync.aligned.m8n8.x4.shared.b16 {%0,%1,%2,%3}, [%4];"
                 : "=r"(r[0]), "=r"(r[1]), "=r"(r[2]), "=r"(r[3]) : "r"(addr));
}

__device__ __forceinline__ void mma_f16(float* c, const uint32_t* a, uint32_t b0, uint32_t b1) {
    asm volatile("mma.sync.aligned.m16n8k16.row.col.f32.f16.f16.f32 "
                 "{%0,%1,%2,%3}, {%4,%5,%6,%7}, {%8,%9}, {%0,%1,%2,%3};"
                 : "+f"(c[0]), "+f"(c[1]), "+f"(c[2]), "+f"(c[3])
                 : "r"(a[0]), "r"(a[1]), "r"(a[2]), "r"(a[3]), "r"(b0), "r"(b1));
}

__device__ __forceinline__ unsigned key_xform(float v) {
    unsigned u = __float_as_uint(v);
    return (u & 0x80000000u) ? ~u : (u | 0x80000000u);
}

// ---------------- split fp32 -> (fp16 hi, fp16 lo-residual) ----------------
__global__ void split_kernel(const float* __restrict__ src,
                             __half* __restrict__ hi,
                             __half* __restrict__ lo, int n4)
{
    int i = blockIdx.x * blockDim.x + threadIdx.x;
    const int stride = gridDim.x * blockDim.x;
    for (; i < n4; i += stride) {
        float4 v = ((const float4*)src)[i];
        __half h0 = __float2half_rn(v.x);
        __half h1 = __float2half_rn(v.y);
        __half h2 = __float2half_rn(v.z);
        __half h3 = __float2half_rn(v.w);
        __half2 ha; ha.x = h0; ha.y = h1;
        __half2 hb; hb.x = h2; hb.y = h3;
        ((__half2*)hi)[2 * i]     = ha;
        ((__half2*)hi)[2 * i + 1] = hb;
        __half2 la, lb;
        la.x = __float2half_rn(v.x - __half2float(h0));
        la.y = __float2half_rn(v.y - __half2float(h1));
        lb.x = __float2half_rn(v.z - __half2float(h2));
        lb.y = __float2half_rn(v.w - __half2float(h3));
        ((__half2*)lo)[2 * i]     = la;
        ((__half2*)lo)[2 * i + 1] = lb;
    }
}

// ---------------- W2 transpose [10][2000]->[2000][12] + boost table ----------------
__global__ void w2t_kernel(const float* __restrict__ W2, const float* __restrict__ duty,
                           float* __restrict__ W2t, float* __restrict__ boost)
{
    const int i = blockIdx.x * blockDim.x + threadIdx.x;
    if (i < NHID) {
        float v[12];
        #pragma unroll
        for (int c = 0; c < NCLS; c++) v[c] = W2[c * NHID + i];
        v[10] = 0.f; v[11] = 0.f;
        float4* dst = (float4*)(W2t + (size_t)i * 12);
        dst[0] = make_float4(v[0], v[1], v[2], v[3]);
        dst[1] = make_float4(v[4], v[5], v[6], v[7]);
        dst[2] = make_float4(v[8], v[9], v[10], v[11]);
        boost[i] = expf(0.1f - duty[i]);   // boostStrength=1, targetDensity=k/n=0.1
    }
}

// ---------------- HMMA GEMM1: h = x @ W1^T + b1 (split-fp16, 3 terms) ----------------
#define BM 128
#define BN 128
#define BKG 32
#define NCHUNK 25
#define MAT_SZ (128 * 64)           // 8192 B
#define STAGE_SZ (4 * MAT_SZ)       // 32768 B
#define NSTAGE 3
#define SMEM_GEMM (NSTAGE * STAGE_SZ)   // 98304 B -> 2 CTAs/SM

__global__ __launch_bounds__(256, 2)
void gemm1_mma(const __half* __restrict__ xhi, const __half* __restrict__ xlo,
               const __half* __restrict__ whi, const __half* __restrict__ wlo,
               const float* __restrict__ bias, float* __restrict__ H)
{
    extern __shared__ __align__(1024) char smem[];
    const uint32_t sb = smem_u32(smem);
    const int tid = threadIdx.x;
    const int lane = tid & 31;
    const int wid = tid >> 5;
    const int wm = wid & 1;
    const int wn = wid >> 1;
    const int m0 = blockIdx.y * BM;
    const int n0 = blockIdx.x * BN;

    const __half* srcp[8];
    uint32_t      dsto[8];
    bool          nv[8];
    int           segl[8];
    #pragma unroll
    for (int j = 0; j < 8; j++) {
        const int mat = j >> 1;                        // 0:Ahi 1:Alo 2:Bhi 3:Blo
        const int idx = (j & 1) * 256 + tid;
        const int row = idx >> 2;
        const int seg = idx & 3;
        segl[j] = seg;
        const uint32_t sseg = (uint32_t)seg ^ (((uint32_t)row >> 1) & 3u);
        dsto[j] = (uint32_t)(mat * MAT_SZ + row * 64 + sseg * 16);
        if (mat < 2) {
            srcp[j] = (mat == 0 ? xhi : xlo) + (size_t)(m0 + row) * IN_DIM + seg * 8;
            nv[j] = true;
        } else {
            const int n = n0 + row;
            nv[j] = (n < NHID);
            const int nn = nv[j] ? n : 0;
            srcp[j] = (mat == 2 ? whi : wlo) + (size_t)nn * IN_DIM + seg * 8;
        }
    }

    auto load_chunk = [&](int c) {
        const uint32_t base = sb + (uint32_t)(c % NSTAGE) * STAGE_SZ;
        const int klim = IN_DIM - c * BKG;
        #pragma unroll
        for (int j = 0; j < 8; j++) {
            const bool valid = nv[j] && (segl[j] * 8 < klim);
            cpa16z(base + dsto[j], srcp[j] + (size_t)c * BKG, valid);
        }
        asm volatile("cp.async.commit_group;");
    };

    float acc[4][4][4];
    #pragma unroll
    for (int i = 0; i < 4; i++)
        #pragma unroll
        for (int j = 0; j < 4; j++)
            #pragma unroll
            for (int q = 0; q < 4; q++) acc[i][j][q] = 0.f;

    const uint32_t aSwz = (uint32_t)(((lane & 15) >> 1) & 3);
    const uint32_t bSwz = (uint32_t)(((lane & 7) >> 1) & 3);
    const uint32_t aChunkHi = (uint32_t)(lane >> 4);
    const uint32_t bChunkHi = (uint32_t)((lane >> 3) & 1);
    const uint32_t aRow = (uint32_t)((wm * 64 + (lane & 15)) * 64);
    const uint32_t bRow = (uint32_t)((wn * 32 + (lane >> 4) * 8 + (lane & 7)) * 64);

    load_chunk(0);
    load_chunk(1);

    for (int c = 0; c < NCHUNK; c++) {
        if (c + 1 < NCHUNK) {
            asm volatile("cp.async.wait_group 1;");
        } else {
            asm volatile("cp.async.wait_group 0;");
        }
        __syncthreads();

        if (c + 2 < NCHUNK) load_chunk(c + 2);

        const uint32_t base = sb + (uint32_t)(c % NSTAGE) * STAGE_SZ;
        #pragma unroll
        for (int kk = 0; kk < 2; kk++) {
            const uint32_t aOff = (((uint32_t)(kk * 2) + aChunkHi) ^ aSwz) * 16;
            const uint32_t bOff = (((uint32_t)(kk * 2) + bChunkHi) ^ bSwz) * 16;

            uint32_t ra[2][4][4];
            #pragma unroll
            for (int i = 0; i < 4; i++) {
                const uint32_t ao = base + aRow + (uint32_t)(i * 1024) + aOff;
                ldsm_x4(ao,          ra[0][i]);
                ldsm_x4(ao + MAT_SZ, ra[1][i]);
            }
            uint32_t rb[2][2][4];
            #pragma unroll
            for (int jj = 0; jj < 2; jj++) {
                const uint32_t bo = base + 2 * MAT_SZ + bRow + (uint32_t)(jj * 1024) + bOff;
                ldsm_x4(bo,          rb[0][jj]);
                ldsm_x4(bo + MAT_SZ, rb[1][jj]);
            }

            #pragma unroll
            for (int t = 0; t < 3; t++) {
                const int ta = (t == 2) ? 1 : 0;
                const int tb = (t == 1) ? 1 : 0;
                #pragma unroll
                for (int i = 0; i < 4; i++) {
                    #pragma unroll
                    for (int j = 0; j < 4; j++) {
                        const int jj = j >> 1;
                        const int pr = (j & 1) * 2;
                        mma_f16(acc[i][j], ra[ta][i], rb[tb][jj][pr], rb[tb][jj][pr + 1]);
                    }
                }
            }
        }
    }

    #pragma unroll
    for (int i = 0; i < 4; i++) {
        const int r0 = m0 + wm * 64 + i * 16 + (lane >> 2);
        #pragma unroll
        for (int j = 0; j < 4; j++) {
            const int col = n0 + wn * 32 + j * 8 + (lane & 3) * 2;
            if (col < NHID) {
                const float bx = __ldg(bias + col);
                const float by = __ldg(bias + col + 1);
                float2 v0 = make_float2(acc[i][j][0] + bx, acc[i][j][1] + by);
                float2 v1 = make_float2(acc[i][j][2] + bx, acc[i][j][3] + by);
                *(float2*)(H + (size_t)r0 * NHID + col)       = v0;
                *(float2*)(H + (size_t)(r0 + 8) * NHID + col) = v1;
            }
        }
    }
}

// ---------------- Kernel B: warp-per-row k-winners ----------------
// Round-12 structure; p1 uses plain smem atomics; p3 uses one packed scan per chunk.
#define WPC 8
#define NV4 (NHID / 4)     // 500 packed entries (4 keys16 each)
#define CCAP 64
#define WCAP 288

__global__ __launch_bounds__(256)
void kwin_head_kernel(const float* __restrict__ H,
                      const float* __restrict__ W2t,
                      const float* __restrict__ b2v,
                      const float* __restrict__ boost,
                      float* __restrict__ out)
{
    __shared__ uint2          keysS[WPC][NV4];
    __shared__ unsigned       histS[WPC][256];
    __shared__ unsigned       candKeyS[WPC][CCAP];
    __shared__ unsigned short candIdxS[WPC][CCAP];
    __shared__ unsigned short wlistS[WPC][WCAP];

    const int lane = threadIdx.x & 31;
    const int warp = threadIdx.x >> 5;
    const int row  = blockIdx.x * WPC + warp;
    const float*  hrow = H + (size_t)row * NHID;
    const float4* h4p  = (const float4*)hrow;
    const float4* b4p  = (const float4*)boost;
    uint2*          keys2 = keysS[warp];
    unsigned*       hist  = histS[warp];
    unsigned*       ckey  = candKeyS[warp];
    unsigned short* cidx  = candIdxS[warp];
    unsigned short* wlist = wlistS[warp];
    const unsigned FULL = 0xFFFFFFFFu;
    const unsigned laneLT = (1u << lane) - 1u;

    auto suffix_select = [&](int K, unsigned& binOut, int& kremOut) {
        unsigned gsum[8];
        #pragma unroll
        for (int g = 0; g < 8; g++) {
            unsigned s = hist[g * 32 + lane];
            #pragma unroll
            for (int off = 16; off; off >>= 1) s += __shfl_xor_sync(FULL, s, off);
            gsum[g] = s;
        }
        int gstar = 0; unsigned above = 0; unsigned run = 0;
        #pragma unroll
        for (int g = 7; g >= 0; g--) {
            if (run < (unsigned)K && run + gsum[g] >= (unsigned)K) { gstar = g; above = run; }
            run += gsum[g];
        }
        const unsigned v = hist[gstar * 32 + lane];
        unsigned suf = v;
        #pragma unroll
        for (int off = 1; off < 32; off <<= 1) {
            const unsigned t = __shfl_down_sync(FULL, suf, off);
            if (lane + off < 32) suf += t;
        }
        const unsigned suft  = suf + above;
        const unsigned below = suft - v;
        const bool found = (suft >= (unsigned)K) && (below < (unsigned)K);
        const unsigned fm = __ballot_sync(FULL, found);
        const int src = __ffs(fm) - 1;
        binOut  = (unsigned)(gstar * 32 + src);
        kremOut = __shfl_sync(FULL, (int)((unsigned)K - below), src);
    };

    #pragma unroll
    for (int g = 0; g < 8; g++) hist[g * 32 + lane] = 0u;
    __syncwarp();

    // ---- pass 1 (global): build keys16 -> smem, top-byte histogram (plain atomics) ----
    for (int v0 = 0; v0 < NV4; v0 += 32) {
        const int v = v0 + lane;
        if (v < NV4) {
            const float4 h4 = h4p[v];
            const float4 b4 = b4p[v];
            unsigned k16[4];
            k16[0] = key_xform(h4.x * b4.x) >> 16;
            k16[1] = key_xform(h4.y * b4.y) >> 16;
            k16[2] = key_xform(h4.z * b4.z) >> 16;
            k16[3] = key_xform(h4.w * b4.w) >> 16;
            keys2[v] = make_uint2(k16[0] | (k16[1] << 16), k16[2] | (k16[3] << 16));
            #pragma unroll
            for (int q = 0; q < 4; q++)
                atomicAdd(&hist[k16[q] >> 8], 1u);
        }
    }
    __syncwarp();

    unsigned b1; int k1;
    suffix_select(KWIN, b1, k1);

    #pragma unroll
    for (int g = 0; g < 8; g++) hist[g * 32 + lane] = 0u;
    __syncwarp();

    // ---- pass 2 (smem): low-byte histogram among top-byte == b1 ----
    for (int v0 = 0; v0 < NV4; v0 += 32) {
        const int v = v0 + lane;
        if (v < NV4) {
            const uint2 kk = keys2[v];
            const unsigned k16[4] = {kk.x & 0xFFFFu, kk.x >> 16, kk.y & 0xFFFFu, kk.y >> 16};
            #pragma unroll
            for (int q = 0; q < 4; q++)
                if ((k16[q] >> 8) == b1) atomicAdd(&hist[k16[q] & 255u], 1u);
        }
    }
    __syncwarp();

    unsigned b2bin; int k2;
    suffix_select(k1, b2bin, k2);
    const unsigned thr16 = (b1 << 8) | b2bin;

    // ---- pass 3 (smem): packed-scan compaction of strict winners + boundary candidates ----
    int wcnt = 0, ccnt = 0;
    for (int v0 = 0; v0 < NV4; v0 += 32) {
        const int v = v0 + lane;
        const bool in = v < NV4;
        unsigned k16[4]; bool sw[4], cq[4];
        unsigned nw = 0, nc = 0;
        if (in) {
            const uint2 kk = keys2[v];
            k16[0] = kk.x & 0xFFFFu; k16[1] = kk.x >> 16;
            k16[2] = kk.y & 0xFFFFu; k16[3] = kk.y >> 16;
            #pragma unroll
            for (int q = 0; q < 4; q++) {
                sw[q] = (k16[q] > thr16);
                cq[q] = (k16[q] == thr16);
                nw += sw[q]; nc += cq[q];
            }
        } else {
            #pragma unroll
            for (int q = 0; q < 4; q++) { sw[q] = false; cq[q] = false; }
        }
        // packed inclusive scan of (nc<<16 | nw)
        unsigned pk = (nc << 16) | nw;
        unsigned sc = pk;
        #pragma unroll
        for (int off = 1; off < 32; off <<= 1) {
            const unsigned t = __shfl_up_sync(FULL, sc, off);
            if (lane >= off) sc += t;
        }
        const unsigned tot = __shfl_sync(FULL, sc, 31);
        const unsigned exc = sc - pk;
        int wpos = wcnt + (int)(exc & 0xFFFFu);
        int cpos = ccnt + (int)(exc >> 16);
        if (in) {
            #pragma unroll
            for (int q = 0; q < 4; q++) {
                if (sw[q]) {
                    if (wpos < WCAP) wlist[wpos] = (unsigned short)(v * 4 + q);
                    wpos++;
                }
                if (cq[q]) {
                    if (cpos < CCAP) cidx[cpos] = (unsigned short)(v * 4 + q);
                    cpos++;
                }
            }
        }
        wcnt += (int)(tot & 0xFFFFu);
        ccnt += (int)(tot >> 16);
    }
    __syncwarp();
    const int L = (ccnt < CCAP) ? ccnt : CCAP;
    int Wn = (wcnt < WCAP) ? wcnt : WCAP;

    // boundary candidates: full keys, exact rank (key desc, idx asc), append winners
    for (int j = lane; j < L; j += 32) {
        const int ii = cidx[j];
        ckey[j] = key_xform(__ldg(&hrow[ii]) * __ldg(&boost[ii]));
    }
    __syncwarp();
    for (int j0 = 0; j0 < L; j0 += 32) {
        const int j = j0 + lane;
        bool win = false;
        int ii = 0;
        if (j < L) {
            const unsigned ku = ckey[j];
            ii = cidx[j];
            int rank = 0;
            for (int t = 0; t < L; t++) {
                const unsigned kt = ckey[t];
                rank += (kt > ku) || (kt == ku && (int)cidx[t] < ii);
            }
            win = (rank < k2);
        }
        const unsigned mask = __ballot_sync(FULL, win);
        if (win) {
            const int pos = Wn + __popc(mask & laneLT);
            if (pos < WCAP) wlist[pos] = (unsigned short)ii;
        }
        Wn += __popc(mask);
    }
    __syncwarp();
    if (Wn > WCAP) Wn = WCAP;

    // ---- pass 4: dense accumulation over compacted winner list ----
    float acc[NCLS];
    #pragma unroll
    for (int c = 0; c < NCLS; c++) acc[c] = 0.f;

    for (int j = lane; j < Wn; j += 32) {
        const int i = wlist[j];
        const float hv = __ldg(&hrow[i]);
        const float4* wp = (const float4*)(W2t + (size_t)i * 12);
        const float4 w0 = __ldg(wp);
        const float4 w1 = __ldg(wp + 1);
        const float4 w2 = __ldg(wp + 2);
        acc[0] = fmaf(hv, w0.x, acc[0]);
        acc[1] = fmaf(hv, w0.y, acc[1]);
        acc[2] = fmaf(hv, w0.z, acc[2]);
        acc[3] = fmaf(hv, w0.w, acc[3]);
        acc[4] = fmaf(hv, w1.x, acc[4]);
        acc[5] = fmaf(hv, w1.y, acc[5]);
        acc[6] = fmaf(hv, w1.z, acc[6]);
        acc[7] = fmaf(hv, w1.w, acc[7]);
        acc[8] = fmaf(hv, w2.x, acc[8]);
        acc[9] = fmaf(hv, w2.y, acc[9]);
    }

    #pragma unroll
    for (int off = 16; off; off >>= 1)
        #pragma unroll
        for (int c = 0; c < NCLS; c++)
            acc[c] += __shfl_xor_sync(FULL, acc[c], off);

    if (lane == 0) {
        float lg[NCLS];
        #pragma unroll
        for (int c = 0; c < NCLS; c++) lg[c] = acc[c] + __ldg(&b2v[c]);
        float mx = lg[0];
        #pragma unroll
        for (int c = 1; c < NCLS; c++) mx = fmaxf(mx, lg[c]);
        float se = 0.f;
        #pragma unroll
        for (int c = 0; c < NCLS; c++) se += expf(lg[c] - mx);
        const float lse = mx + logf(se);
        float* orow = out + (size_t)row * NCLS;
        #pragma unroll
        for (int c = 0; c < NCLS; c++) orow[c] = lg[c] - lse;
    }
}

// ---------------- launch ----------------
extern "C" void kernel_launch(void* const* d_in, const int* in_sizes, int n_in,
                              void* d_out, int out_size)
{
    const float* x    = (const float*)d_in[0];   // [16384, 784]
    const float* W1   = (const float*)d_in[1];   // [2000, 784]
    const float* b1   = (const float*)d_in[2];   // [2000]
    const float* W2   = (const float*)d_in[3];   // [10, 2000]
    const float* b2   = (const float*)d_in[4];   // [10]
    const float* duty = (const float*)d_in[5];   // [2000]
    float* out = (float*)d_out;                  // [16384, 10]

    float*  h;    cudaGetSymbolAddress((void**)&h,   g_h);
    __half* xhi;  cudaGetSymbolAddress((void**)&xhi, g_xhi);
    __half* xlo;  cudaGetSymbolAddress((void**)&xlo, g_xlo);
    __half* whi;  cudaGetSymbolAddress((void**)&whi, g_whi);
    __half* wlo;  cudaGetSymbolAddress((void**)&wlo, g_wlo);
    float*  w2t;  cudaGetSymbolAddress((void**)&w2t, g_w2t);
    float*  bst;  cudaGetSymbolAddress((void**)&bst, g_boost);

    split_kernel<<<1024, 256>>>(x,  xhi, xlo, (BATCH * IN_DIM) / 4);
    split_kernel<<<512,  256>>>(W1, whi, wlo, (NHID  * IN_DIM) / 4);
    w2t_kernel<<<(NHID + 255) / 256, 256>>>(W2, duty, w2t, bst);

    cudaFuncSetAttribute(gemm1_mma, cudaFuncAttributeMaxDynamicSharedMemorySize, SMEM_GEMM);
    dim3 gridG((NHID + BN - 1) / BN, BATCH / BM);   // (16, 128)
    gemm1_mma<<<gridG, 256, SMEM_GEMM>>>(xhi, xlo, whi, wlo, b1, h);

    kwin_head_kernel<<<BATCH / WPC, 256>>>(h, w2t, b2, bst, out);
}

// round 16
// speedup vs baseline: 1.1489x; 1.0151x over previous
#include <cuda_runtime.h>
#include <cuda_fp16.h>
#include <cstdint>
#include <math.h>

// Problem constants
#define BATCH   16384
#define IN_DIM  784
#define NHID    2000
#define KWIN    200
#define NCLS    10

// ---------------- device scratch ----------------
__device__ __align__(256) float  g_h  [(size_t)BATCH * NHID];
__device__ __align__(256) __half g_xhi[(size_t)BATCH * IN_DIM];
__device__ __align__(256) __half g_xlo[(size_t)BATCH * IN_DIM];
__device__ __align__(256) __half g_whi[(size_t)NHID * IN_DIM];
__device__ __align__(256) __half g_wlo[(size_t)NHID * IN_DIM];
__device__ __align__(256) float  g_w2t[(size_t)NHID * 12];
__device__ __align__(256) float  g_boost[NHID];

// ---------------- helpers ----------------
__device__ __forceinline__ uint32_t smem_u32(const void* p) {
    uint32_t a;
    asm("{ .reg .u64 t; cvta.to.shared.u64 t, %1; cvt.u32.u64 %0, t; }" : "=r"(a) : "l"(p));
    return a;
}

__device__ __forceinline__ void cpa16z(uint32_t dst, const void* src, bool valid) {
    int sz = valid ? 16 : 0;
    asm volatile("cp.async.cg.shared.global [%0], [%1], 16, %2;"
                 :: "r"(dst), "l"(src), "r"(sz));
}

__device__ __forceinline__ void ldsm_x4(uint32_t addr, uint32_t* r) {
    asm volatile("ldmatrix.sync.aligned.m8n8.x4.shared.b16 {%0,%1,%2,%3}, [%4];"
                 : "=r"(r[0]), "=r"(r[1]), "=r"(r[2]), "=r"(r[3]) : "r"(addr));
}

__device__ __forceinline__ void mma_f16(float* c, const uint32_t* a, uint32_t b0, uint32_t b1) {
    asm volatile("mma.sync.aligned.m16n8k16.row.col.f32.f16.f16.f32 "
                 "{%0,%1,%2,%3}, {%4,%5,%6,%7}, {%8,%9}, {%0,%1,%2,%3};"
                 : "+f"(c[0]), "+f"(c[1]), "+f"(c[2]), "+f"(c[3])
                 : "r"(a[0]), "r"(a[1]), "r"(a[2]), "r"(a[3]), "r"(b0), "r"(b1));
}

__device__ __forceinline__ unsigned key_xform(float v) {
    unsigned u = __float_as_uint(v);
    return (u & 0x80000000u) ? ~u : (u | 0x80000000u);
}

// ---------------- fused prep: split x, split W1, transpose W2, boost ----------------
__device__ __forceinline__ void split4(const float* __restrict__ src,
                                       __half* __restrict__ hi,
                                       __half* __restrict__ lo, int i)
{
    float4 v = ((const float4*)src)[i];
    __half h0 = __float2half_rn(v.x);
    __half h1 = __float2half_rn(v.y);
    __half h2 = __float2half_rn(v.z);
    __half h3 = __float2half_rn(v.w);
    __half2 ha; ha.x = h0; ha.y = h1;
    __half2 hb; hb.x = h2; hb.y = h3;
    ((__half2*)hi)[2 * i]     = ha;
    ((__half2*)hi)[2 * i + 1] = hb;
    __half2 la, lb;
    la.x = __float2half_rn(v.x - __half2float(h0));
    la.y = __float2half_rn(v.y - __half2float(h1));
    lb.x = __float2half_rn(v.z - __half2float(h2));
    lb.y = __float2half_rn(v.w - __half2float(h3));
    ((__half2*)lo)[2 * i]     = la;
    ((__half2*)lo)[2 * i + 1] = lb;
}

#define N4X ((BATCH * IN_DIM) / 4)
#define N4W ((NHID * IN_DIM) / 4)

__global__ void prep_kernel(const float* __restrict__ x,  const float* __restrict__ W1,
                            const float* __restrict__ W2, const float* __restrict__ duty,
                            __half* __restrict__ xhi, __half* __restrict__ xlo,
                            __half* __restrict__ whi, __half* __restrict__ wlo,
                            float* __restrict__ W2t, float* __restrict__ boost)
{
    const int gid = blockIdx.x * blockDim.x + threadIdx.x;
    const int stride = gridDim.x * blockDim.x;

    for (int i = gid; i < N4X; i += stride) split4(x,  xhi, xlo, i);
    for (int i = gid; i < N4W; i += stride) split4(W1, whi, wlo, i);
    for (int i = gid; i < NHID; i += stride) {
        float v[12];
        #pragma unroll
        for (int c = 0; c < NCLS; c++) v[c] = W2[c * NHID + i];
        v[10] = 0.f; v[11] = 0.f;
        float4* dst = (float4*)(W2t + (size_t)i * 12);
        dst[0] = make_float4(v[0], v[1], v[2], v[3]);
        dst[1] = make_float4(v[4], v[5], v[6], v[7]);
        dst[2] = make_float4(v[8], v[9], v[10], v[11]);
        boost[i] = expf(0.1f - duty[i]);   // boostStrength=1, targetDensity=k/n=0.1
    }
}

// ---------------- HMMA GEMM1: h = x @ W1^T + b1 (split-fp16, 3 terms) ----------------
#define BM 128
#define BN 128
#define BKG 32
#define NCHUNK 25
#define MAT_SZ (128 * 64)           // 8192 B
#define STAGE_SZ (4 * MAT_SZ)       // 32768 B
#define NSTAGE 3
#define SMEM_GEMM (NSTAGE * STAGE_SZ)   // 98304 B -> 2 CTAs/SM

__global__ __launch_bounds__(256, 2)
void gemm1_mma(const __half* __restrict__ xhi, const __half* __restrict__ xlo,
               const __half* __restrict__ whi, const __half* __restrict__ wlo,
               const float* __restrict__ bias, float* __restrict__ H)
{
    extern __shared__ __align__(1024) char smem[];
    const uint32_t sb = smem_u32(smem);
    const int tid = threadIdx.x;
    const int lane = tid & 31;
    const int wid = tid >> 5;
    const int wm = wid & 1;
    const int wn = wid >> 1;
    const int m0 = blockIdx.y * BM;
    const int n0 = blockIdx.x * BN;

    const __half* srcp[8];
    uint32_t      dsto[8];
    bool          nv[8];
    int           segl[8];
    #pragma unroll
    for (int j = 0; j < 8; j++) {
        const int mat = j >> 1;                        // 0:Ahi 1:Alo 2:Bhi 3:Blo
        const int idx = (j & 1) * 256 + tid;
        const int row = idx >> 2;
        const int seg = idx & 3;
        segl[j] = seg;
        const uint32_t sseg = (uint32_t)seg ^ (((uint32_t)row >> 1) & 3u);
        dsto[j] = (uint32_t)(mat * MAT_SZ + row * 64 + sseg * 16);
        if (mat < 2) {
            srcp[j] = (mat == 0 ? xhi : xlo) + (size_t)(m0 + row) * IN_DIM + seg * 8;
            nv[j] = true;
        } else {
            const int n = n0 + row;
            nv[j] = (n < NHID);
            const int nn = nv[j] ? n : 0;
            srcp[j] = (mat == 2 ? whi : wlo) + (size_t)nn * IN_DIM + seg * 8;
        }
    }

    auto load_chunk = [&](int c) {
        const uint32_t base = sb + (uint32_t)(c % NSTAGE) * STAGE_SZ;
        const int klim = IN_DIM - c * BKG;
        #pragma unroll
        for (int j = 0; j < 8; j++) {
            const bool valid = nv[j] && (segl[j] * 8 < klim);
            cpa16z(base + dsto[j], srcp[j] + (size_t)c * BKG, valid);
        }
        asm volatile("cp.async.commit_group;");
    };

    float acc[4][4][4];
    #pragma unroll
    for (int i = 0; i < 4; i++)
        #pragma unroll
        for (int j = 0; j < 4; j++)
            #pragma unroll
            for (int q = 0; q < 4; q++) acc[i][j][q] = 0.f;

    const uint32_t aSwz = (uint32_t)(((lane & 15) >> 1) & 3);
    const uint32_t bSwz = (uint32_t)(((lane & 7) >> 1) & 3);
    const uint32_t aChunkHi = (uint32_t)(lane >> 4);
    const uint32_t bChunkHi = (uint32_t)((lane >> 3) & 1);
    const uint32_t aRow = (uint32_t)((wm * 64 + (lane & 15)) * 64);
    const uint32_t bRow = (uint32_t)((wn * 32 + (lane >> 4) * 8 + (lane & 7)) * 64);

    load_chunk(0);
    load_chunk(1);

    for (int c = 0; c < NCHUNK; c++) {
        if (c + 1 < NCHUNK) {
            asm volatile("cp.async.wait_group 1;");
        } else {
            asm volatile("cp.async.wait_group 0;");
        }
        __syncthreads();

        if (c + 2 < NCHUNK) load_chunk(c + 2);

        const uint32_t base = sb + (uint32_t)(c % NSTAGE) * STAGE_SZ;
        #pragma unroll
        for (int kk = 0; kk < 2; kk++) {
            const uint32_t aOff = (((uint32_t)(kk * 2) + aChunkHi) ^ aSwz) * 16;
            const uint32_t bOff = (((uint32_t)(kk * 2) + bChunkHi) ^ bSwz) * 16;

            uint32_t ra[2][4][4];
            #pragma unroll
            for (int i = 0; i < 4; i++) {
                const uint32_t ao = base + aRow + (uint32_t)(i * 1024) + aOff;
                ldsm_x4(ao,          ra[0][i]);
                ldsm_x4(ao + MAT_SZ, ra[1][i]);
            }
            uint32_t rb[2][2][4];
            #pragma unroll
            for (int jj = 0; jj < 2; jj++) {
                const uint32_t bo = base + 2 * MAT_SZ + bRow + (uint32_t)(jj * 1024) + bOff;
                ldsm_x4(bo,          rb[0][jj]);
                ldsm_x4(bo + MAT_SZ, rb[1][jj]);
            }

            #pragma unroll
            for (int t = 0; t < 3; t++) {
                const int ta = (t == 2) ? 1 : 0;
                const int tb = (t == 1) ? 1 : 0;
                #pragma unroll
                for (int i = 0; i < 4; i++) {
                    #pragma unroll
                    for (int j = 0; j < 4; j++) {
                        const int jj = j >> 1;
                        const int pr = (j & 1) * 2;
                        mma_f16(acc[i][j], ra[ta][i], rb[tb][jj][pr], rb[tb][jj][pr + 1]);
                    }
                }
            }
        }
    }

    #pragma unroll
    for (int i = 0; i < 4; i++) {
        const int r0 = m0 + wm * 64 + i * 16 + (lane >> 2);
        #pragma unroll
        for (int j = 0; j < 4; j++) {
            const int col = n0 + wn * 32 + j * 8 + (lane & 3) * 2;
            if (col < NHID) {
                const float bx = __ldg(bias + col);
                const float by = __ldg(bias + col + 1);
                float2 v0 = make_float2(acc[i][j][0] + bx, acc[i][j][1] + by);
                float2 v1 = make_float2(acc[i][j][2] + bx, acc[i][j][3] + by);
                *(float2*)(H + (size_t)r0 * NHID + col)       = v0;
                *(float2*)(H + (size_t)(r0 + 8) * NHID + col) = v1;
            }
        }
    }
}

// ---------------- Kernel B: warp-per-row k-winners (WPC=4, finer CTAs) ----------------
#define WPC 4
#define TB_KW (WPC * 32)
#define NV4 (NHID / 4)     // 500 packed entries (4 keys16 each)
#define CCAP 64
#define WCAP 288

__global__ __launch_bounds__(TB_KW)
void kwin_head_kernel(const float* __restrict__ H,
                      const float* __restrict__ W2t,
                      const float* __restrict__ b2v,
                      const float* __restrict__ boost,
                      float* __restrict__ out)
{
    __shared__ uint2          keysS[WPC][NV4];
    __shared__ unsigned       histS[WPC][256];
    __shared__ unsigned       candKeyS[WPC][CCAP];
    __shared__ unsigned short candIdxS[WPC][CCAP];
    __shared__ unsigned short wlistS[WPC][WCAP];

    const int lane = threadIdx.x & 31;
    const int warp = threadIdx.x >> 5;
    const int row  = blockIdx.x * WPC + warp;
    const float*  hrow = H + (size_t)row * NHID;
    const float4* h4p  = (const float4*)hrow;
    const float4* b4p  = (const float4*)boost;
    uint2*          keys2 = keysS[warp];
    unsigned*       hist  = histS[warp];
    unsigned*       ckey  = candKeyS[warp];
    unsigned short* cidx  = candIdxS[warp];
    unsigned short* wlist = wlistS[warp];
    const unsigned FULL = 0xFFFFFFFFu;
    const unsigned laneLT = (1u << lane) - 1u;

    auto suffix_select = [&](int K, unsigned& binOut, int& kremOut) {
        unsigned gsum[8];
        #pragma unroll
        for (int g = 0; g < 8; g++) {
            unsigned s = hist[g * 32 + lane];
            #pragma unroll
            for (int off = 16; off; off >>= 1) s += __shfl_xor_sync(FULL, s, off);
            gsum[g] = s;
        }
        int gstar = 0; unsigned above = 0; unsigned run = 0;
        #pragma unroll
        for (int g = 7; g >= 0; g--) {
            if (run < (unsigned)K && run + gsum[g] >= (unsigned)K) { gstar = g; above = run; }
            run += gsum[g];
        }
        const unsigned v = hist[gstar * 32 + lane];
        unsigned suf = v;
        #pragma unroll
        for (int off = 1; off < 32; off <<= 1) {
            const unsigned t = __shfl_down_sync(FULL, suf, off);
            if (lane + off < 32) suf += t;
        }
        const unsigned suft  = suf + above;
        const unsigned below = suft - v;
        const bool found = (suft >= (unsigned)K) && (below < (unsigned)K);
        const unsigned fm = __ballot_sync(FULL, found);
        const int src = __ffs(fm) - 1;
        binOut  = (unsigned)(gstar * 32 + src);
        kremOut = __shfl_sync(FULL, (int)((unsigned)K - below), src);
    };

    #pragma unroll
    for (int g = 0; g < 8; g++) hist[g * 32 + lane] = 0u;
    __syncwarp();

    // ---- pass 1 (global): build keys16 -> smem, top-byte histogram (plain atomics) ----
    for (int v0 = 0; v0 < NV4; v0 += 32) {
        const int v = v0 + lane;
        if (v < NV4) {
            const float4 h4 = h4p[v];
            const float4 b4 = b4p[v];
            unsigned k16[4];
            k16[0] = key_xform(h4.x * b4.x) >> 16;
            k16[1] = key_xform(h4.y * b4.y) >> 16;
            k16[2] = key_xform(h4.z * b4.z) >> 16;
            k16[3] = key_xform(h4.w * b4.w) >> 16;
            keys2[v] = make_uint2(k16[0] | (k16[1] << 16), k16[2] | (k16[3] << 16));
            #pragma unroll
            for (int q = 0; q < 4; q++)
                atomicAdd(&hist[k16[q] >> 8], 1u);
        }
    }
    __syncwarp();

    unsigned b1; int k1;
    suffix_select(KWIN, b1, k1);

    #pragma unroll
    for (int g = 0; g < 8; g++) hist[g * 32 + lane] = 0u;
    __syncwarp();

    // ---- pass 2 (smem): low-byte histogram among top-byte == b1 ----
    for (int v0 = 0; v0 < NV4; v0 += 32) {
        const int v = v0 + lane;
        if (v < NV4) {
            const uint2 kk = keys2[v];
            const unsigned k16[4] = {kk.x & 0xFFFFu, kk.x >> 16, kk.y & 0xFFFFu, kk.y >> 16};
            #pragma unroll
            for (int q = 0; q < 4; q++)
                if ((k16[q] >> 8) == b1) atomicAdd(&hist[k16[q] & 255u], 1u);
        }
    }
    __syncwarp();

    unsigned b2bin; int k2;
    suffix_select(k1, b2bin, k2);
    const unsigned thr16 = (b1 << 8) | b2bin;

    // ---- pass 3 (smem): packed-scan compaction of strict winners + boundary candidates ----
    int wcnt = 0, ccnt = 0;
    for (int v0 = 0; v0 < NV4; v0 += 32) {
        const int v = v0 + lane;
        const bool in = v < NV4;
        unsigned k16[4]; bool sw[4], cq[4];
        unsigned nw = 0, nc = 0;
        if (in) {
            const uint2 kk = keys2[v];
            k16[0] = kk.x & 0xFFFFu; k16[1] = kk.x >> 16;
            k16[2] = kk.y & 0xFFFFu; k16[3] = kk.y >> 16;
            #pragma unroll
            for (int q = 0; q < 4; q++) {
                sw[q] = (k16[q] > thr16);
                cq[q] = (k16[q] == thr16);
                nw += sw[q]; nc += cq[q];
            }
        } else {
            #pragma unroll
            for (int q = 0; q < 4; q++) { sw[q] = false; cq[q] = false; }
        }
        unsigned pk = (nc << 16) | nw;
        unsigned sc = pk;
        #pragma unroll
        for (int off = 1; off < 32; off <<= 1) {
            const unsigned t = __shfl_up_sync(FULL, sc, off);
            if (lane >= off) sc += t;
        }
        const unsigned tot = __shfl_sync(FULL, sc, 31);
        const unsigned exc = sc - pk;
        int wpos = wcnt + (int)(exc & 0xFFFFu);
        int cpos = ccnt + (int)(exc >> 16);
        if (in) {
            #pragma unroll
            for (int q = 0; q < 4; q++) {
                if (sw[q]) {
                    if (wpos < WCAP) wlist[wpos] = (unsigned short)(v * 4 + q);
                    wpos++;
                }
                if (cq[q]) {
                    if (cpos < CCAP) cidx[cpos] = (unsigned short)(v * 4 + q);
                    cpos++;
                }
            }
        }
        wcnt += (int)(tot & 0xFFFFu);
        ccnt += (int)(tot >> 16);
    }
    __syncwarp();
    const int L = (ccnt < CCAP) ? ccnt : CCAP;
    int Wn = (wcnt < WCAP) ? wcnt : WCAP;

    // boundary candidates: full keys, exact rank (key desc, idx asc), append winners
    for (int j = lane; j < L; j += 32) {
        const int ii = cidx[j];
        ckey[j] = key_xform(__ldg(&hrow[ii]) * __ldg(&boost[ii]));
    }
    __syncwarp();
    for (int j0 = 0; j0 < L; j0 += 32) {
        const int j = j0 + lane;
        bool win = false;
        int ii = 0;
        if (j < L) {
            const unsigned ku = ckey[j];
            ii = cidx[j];
            int rank = 0;
            for (int t = 0; t < L; t++) {
                const unsigned kt = ckey[t];
                rank += (kt > ku) || (kt == ku && (int)cidx[t] < ii);
            }
            win = (rank < k2);
        }
        const unsigned mask = __ballot_sync(FULL, win);
        if (win) {
            const int pos = Wn + __popc(mask & laneLT);
            if (pos < WCAP) wlist[pos] = (unsigned short)ii;
        }
        Wn += __popc(mask);
    }
    __syncwarp();
    if (Wn > WCAP) Wn = WCAP;

    // ---- pass 4: dense accumulation over compacted winner list ----
    float acc[NCLS];
    #pragma unroll
    for (int c = 0; c < NCLS; c++) acc[c] = 0.f;

    for (int j = lane; j < Wn; j += 32) {
        const int i = wlist[j];
        const float hv = __ldg(&hrow[i]);
        const float4* wp = (const float4*)(W2t + (size_t)i * 12);
        const float4 w0 = __ldg(wp);
        const float4 w1 = __ldg(wp + 1);
        const float4 w2 = __ldg(wp + 2);
        acc[0] = fmaf(hv, w0.x, acc[0]);
        acc[1] = fmaf(hv, w0.y, acc[1]);
        acc[2] = fmaf(hv, w0.z, acc[2]);
        acc[3] = fmaf(hv, w0.w, acc[3]);
        acc[4] = fmaf(hv, w1.x, acc[4]);
        acc[5] = fmaf(hv, w1.y, acc[5]);
        acc[6] = fmaf(hv, w1.z, acc[6]);
        acc[7] = fmaf(hv, w1.w, acc[7]);
        acc[8] = fmaf(hv, w2.x, acc[8]);
        acc[9] = fmaf(hv, w2.y, acc[9]);
    }

    #pragma unroll
    for (int off = 16; off; off >>= 1)
        #pragma unroll
        for (int c = 0; c < NCLS; c++)
            acc[c] += __shfl_xor_sync(FULL, acc[c], off);

    if (lane == 0) {
        float lg[NCLS];
        #pragma unroll
        for (int c = 0; c < NCLS; c++) lg[c] = acc[c] + __ldg(&b2v[c]);
        float mx = lg[0];
        #pragma unroll
        for (int c = 1; c < NCLS; c++) mx = fmaxf(mx, lg[c]);
        float se = 0.f;
        #pragma unroll
        for (int c = 0; c < NCLS; c++) se += expf(lg[c] - mx);
        const float lse = mx + logf(se);
        float* orow = out + (size_t)row * NCLS;
        #pragma unroll
        for (int c = 0; c < NCLS; c++) orow[c] = lg[c] - lse;
    }
}

// ---------------- launch ----------------
extern "C" void kernel_launch(void* const* d_in, const int* in_sizes, int n_in,
                              void* d_out, int out_size)
{
    const float* x    = (const float*)d_in[0];   // [16384, 784]
    const float* W1   = (const float*)d_in[1];   // [2000, 784]
    const float* b1   = (const float*)d_in[2];   // [2000]
    const float* W2   = (const float*)d_in[3];   // [10, 2000]
    const float* b2   = (const float*)d_in[4];   // [10]
    const float* duty = (const float*)d_in[5];   // [2000]
    float* out = (float*)d_out;                  // [16384, 10]

    float*  h;    cudaGetSymbolAddress((void**)&h,   g_h);
    __half* xhi;  cudaGetSymbolAddress((void**)&xhi, g_xhi);
    __half* xlo;  cudaGetSymbolAddress((void**)&xlo, g_xlo);
    __half* whi;  cudaGetSymbolAddress((void**)&whi, g_whi);
    __half* wlo;  cudaGetSymbolAddress((void**)&wlo, g_wlo);
    float*  w2t;  cudaGetSymbolAddress((void**)&w2t, g_w2t);
    float*  bst;  cudaGetSymbolAddress((void**)&bst, g_boost);

    prep_kernel<<<1184, 256>>>(x, W1, W2, duty, xhi, xlo, whi, wlo, w2t, bst);

    cudaFuncSetAttribute(gemm1_mma, cudaFuncAttributeMaxDynamicSharedMemorySize, SMEM_GEMM);
    dim3 gridG((NHID + BN - 1) / BN, BATCH / BM);   // (16, 128)
    gemm1_mma<<<gridG, 256, SMEM_GEMM>>>(xhi, xlo, whi, wlo, b1, h);

    kwin_head_kernel<<<BATCH / WPC, TB_KW>>>(h, w2t, b2, bst, out);
}

// round 17
// speedup vs baseline: 1.1539x; 1.0044x over previous
#include <cuda_runtime.h>
#include <cuda_fp16.h>
#include <cstdint>
#include <math.h>

// Problem constants
#define BATCH   16384
#define IN_DIM  784
#define NHID    2000
#define KWIN    200
#define NCLS    10

// ---------------- device scratch ----------------
__device__ __align__(256) float  g_h  [(size_t)BATCH * NHID];
__device__ __align__(256) __half g_xhi[(size_t)BATCH * IN_DIM];
__device__ __align__(256) __half g_xlo[(size_t)BATCH * IN_DIM];
__device__ __align__(256) __half g_whi[(size_t)NHID * IN_DIM];
__device__ __align__(256) __half g_wlo[(size_t)NHID * IN_DIM];
__device__ __align__(256) float  g_w2t[(size_t)NHID * 12];
__device__ __align__(256) float  g_boost[NHID];

// ---------------- helpers ----------------
__device__ __forceinline__ uint32_t smem_u32(const void* p) {
    uint32_t a;
    asm("{ .reg .u64 t; cvta.to.shared.u64 t, %1; cvt.u32.u64 %0, t; }" : "=r"(a) : "l"(p));
    return a;
}

__device__ __forceinline__ void cpa16z(uint32_t dst, const void* src, bool valid) {
    int sz = valid ? 16 : 0;
    asm volatile("cp.async.cg.shared.global [%0], [%1], 16, %2;"
                 :: "r"(dst), "l"(src), "r"(sz));
}

__device__ __forceinline__ void ldsm_x4(uint32_t addr, uint32_t* r) {
    asm volatile("ldmatrix.sync.aligned.m8n8.x4.shared.b16 {%0,%1,%2,%3}, [%4];"
                 : "=r"(r[0]), "=r"(r[1]), "=r"(r[2]), "=r"(r[3]) : "r"(addr));
}

__device__ __forceinline__ void mma_f16(float* c, const uint32_t* a, uint32_t b0, uint32_t b1) {
    asm volatile("mma.sync.aligned.m16n8k16.row.col.f32.f16.f16.f32 "
                 "{%0,%1,%2,%3}, {%4,%5,%6,%7}, {%8,%9}, {%0,%1,%2,%3};"
                 : "+f"(c[0]), "+f"(c[1]), "+f"(c[2]), "+f"(c[3])
                 : "r"(a[0]), "r"(a[1]), "r"(a[2]), "r"(a[3]), "r"(b0), "r"(b1));
}

__device__ __forceinline__ unsigned key_xform(float v) {
    unsigned u = __float_as_uint(v);
    return (u & 0x80000000u) ? ~u : (u | 0x80000000u);
}

// ---------------- fused prep: split x, split W1, transpose W2, boost ----------------
__device__ __forceinline__ void split4(const float* __restrict__ src,
                                       __half* __restrict__ hi,
                                       __half* __restrict__ lo, int i)
{
    float4 v = ((const float4*)src)[i];
    __half h0 = __float2half_rn(v.x);
    __half h1 = __float2half_rn(v.y);
    __half h2 = __float2half_rn(v.z);
    __half h3 = __float2half_rn(v.w);
    __half2 ha; ha.x = h0; ha.y = h1;
    __half2 hb; hb.x = h2; hb.y = h3;
    ((__half2*)hi)[2 * i]     = ha;
    ((__half2*)hi)[2 * i + 1] = hb;
    __half2 la, lb;
    la.x = __float2half_rn(v.x - __half2float(h0));
    la.y = __float2half_rn(v.y - __half2float(h1));
    lb.x = __float2half_rn(v.z - __half2float(h2));
    lb.y = __float2half_rn(v.w - __half2float(h3));
    ((__half2*)lo)[2 * i]     = la;
    ((__half2*)lo)[2 * i + 1] = lb;
}

#define N4X ((BATCH * IN_DIM) / 4)
#define N4W ((NHID * IN_DIM) / 4)

__global__ void prep_kernel(const float* __restrict__ x,  const float* __restrict__ W1,
                            const float* __restrict__ W2, const float* __restrict__ duty,
                            __half* __restrict__ xhi, __half* __restrict__ xlo,
                            __half* __restrict__ whi, __half* __restrict__ wlo,
                            float* __restrict__ W2t, float* __restrict__ boost)
{
    const int gid = blockIdx.x * blockDim.x + threadIdx.x;
    const int stride = gridDim.x * blockDim.x;

    for (int i = gid; i < N4X; i += stride) split4(x,  xhi, xlo, i);
    for (int i = gid; i < N4W; i += stride) split4(W1, whi, wlo, i);
    for (int i = gid; i < NHID; i += stride) {
        float v[12];
        #pragma unroll
        for (int c = 0; c < NCLS; c++) v[c] = W2[c * NHID + i];
        v[10] = 0.f; v[11] = 0.f;
        float4* dst = (float4*)(W2t + (size_t)i * 12);
        dst[0] = make_float4(v[0], v[1], v[2], v[3]);
        dst[1] = make_float4(v[4], v[5], v[6], v[7]);
        dst[2] = make_float4(v[8], v[9], v[10], v[11]);
        boost[i] = expf(0.1f - duty[i]);   // boostStrength=1, targetDensity=k/n=0.1
    }
}

// ---------------- HMMA GEMM1: h = x @ W1^T + b1 (split-fp16, 3 terms) ----------------
#define BM 128
#define BN 128
#define BKG 32
#define NCHUNK 25
#define MAT_SZ (128 * 64)           // 8192 B
#define STAGE_SZ (4 * MAT_SZ)       // 32768 B
#define NSTAGE 3
#define SMEM_GEMM (NSTAGE * STAGE_SZ)   // 98304 B -> 2 CTAs/SM

__global__ __launch_bounds__(256, 2)
void gemm1_mma(const __half* __restrict__ xhi, const __half* __restrict__ xlo,
               const __half* __restrict__ whi, const __half* __restrict__ wlo,
               const float* __restrict__ bias, float* __restrict__ H)
{
    extern __shared__ __align__(1024) char smem[];
    const uint32_t sb = smem_u32(smem);
    const int tid = threadIdx.x;
    const int lane = tid & 31;
    const int wid = tid >> 5;
    const int wm = wid & 1;
    const int wn = wid >> 1;
    const int m0 = blockIdx.y * BM;
    const int n0 = blockIdx.x * BN;

    const __half* srcp[8];
    uint32_t      dsto[8];
    bool          nv[8];
    int           segl[8];
    #pragma unroll
    for (int j = 0; j < 8; j++) {
        const int mat = j >> 1;                        // 0:Ahi 1:Alo 2:Bhi 3:Blo
        const int idx = (j & 1) * 256 + tid;
        const int row = idx >> 2;
        const int seg = idx & 3;
        segl[j] = seg;
        const uint32_t sseg = (uint32_t)seg ^ (((uint32_t)row >> 1) & 3u);
        dsto[j] = (uint32_t)(mat * MAT_SZ + row * 64 + sseg * 16);
        if (mat < 2) {
            srcp[j] = (mat == 0 ? xhi : xlo) + (size_t)(m0 + row) * IN_DIM + seg * 8;
            nv[j] = true;
        } else {
            const int n = n0 + row;
            nv[j] = (n < NHID);
            const int nn = nv[j] ? n : 0;
            srcp[j] = (mat == 2 ? whi : wlo) + (size_t)nn * IN_DIM + seg * 8;
        }
    }

    auto load_chunk = [&](int c) {
        const uint32_t base = sb + (uint32_t)(c % NSTAGE) * STAGE_SZ;
        const int klim = IN_DIM - c * BKG;
        #pragma unroll
        for (int j = 0; j < 8; j++) {
            const bool valid = nv[j] && (segl[j] * 8 < klim);
            cpa16z(base + dsto[j], srcp[j] + (size_t)c * BKG, valid);
        }
        asm volatile("cp.async.commit_group;");
    };

    float acc[4][4][4];
    #pragma unroll
    for (int i = 0; i < 4; i++)
        #pragma unroll
        for (int j = 0; j < 4; j++)
            #pragma unroll
            for (int q = 0; q < 4; q++) acc[i][j][q] = 0.f;

    const uint32_t aSwz = (uint32_t)(((lane & 15) >> 1) & 3);
    const uint32_t bSwz = (uint32_t)(((lane & 7) >> 1) & 3);
    const uint32_t aChunkHi = (uint32_t)(lane >> 4);
    const uint32_t bChunkHi = (uint32_t)((lane >> 3) & 1);
    const uint32_t aRow = (uint32_t)((wm * 64 + (lane & 15)) * 64);
    const uint32_t bRow = (uint32_t)((wn * 32 + (lane >> 4) * 8 + (lane & 7)) * 64);

    load_chunk(0);
    load_chunk(1);

    for (int c = 0; c < NCHUNK; c++) {
        if (c + 1 < NCHUNK) {
            asm volatile("cp.async.wait_group 1;");
        } else {
            asm volatile("cp.async.wait_group 0;");
        }
        __syncthreads();

        if (c + 2 < NCHUNK) load_chunk(c + 2);

        const uint32_t base = sb + (uint32_t)(c % NSTAGE) * STAGE_SZ;
        #pragma unroll
        for (int kk = 0; kk < 2; kk++) {
            const uint32_t aOff = (((uint32_t)(kk * 2) + aChunkHi) ^ aSwz) * 16;
            const uint32_t bOff = (((uint32_t)(kk * 2) + bChunkHi) ^ bSwz) * 16;

            uint32_t ra[2][4][4];
            #pragma unroll
            for (int i = 0; i < 4; i++) {
                const uint32_t ao = base + aRow + (uint32_t)(i * 1024) + aOff;
                ldsm_x4(ao,          ra[0][i]);
                ldsm_x4(ao + MAT_SZ, ra[1][i]);
            }
            uint32_t rb[2][2][4];
            #pragma unroll
            for (int jj = 0; jj < 2; jj++) {
                const uint32_t bo = base + 2 * MAT_SZ + bRow + (uint32_t)(jj * 1024) + bOff;
                ldsm_x4(bo,          rb[0][jj]);
                ldsm_x4(bo + MAT_SZ, rb[1][jj]);
            }

            #pragma unroll
            for (int t = 0; t < 3; t++) {
                const int ta = (t == 2) ? 1 : 0;
                const int tb = (t == 1) ? 1 : 0;
                #pragma unroll
                for (int i = 0; i < 4; i++) {
                    #pragma unroll
                    for (int j = 0; j < 4; j++) {
                        const int jj = j >> 1;
                        const int pr = (j & 1) * 2;
                        mma_f16(acc[i][j], ra[ta][i], rb[tb][jj][pr], rb[tb][jj][pr + 1]);
                    }
                }
            }
        }
    }

    #pragma unroll
    for (int i = 0; i < 4; i++) {
        const int r0 = m0 + wm * 64 + i * 16 + (lane >> 2);
        #pragma unroll
        for (int j = 0; j < 4; j++) {
            const int col = n0 + wn * 32 + j * 8 + (lane & 3) * 2;
            if (col < NHID) {
                const float bx = __ldg(bias + col);
                const float by = __ldg(bias + col + 1);
                float2 v0 = make_float2(acc[i][j][0] + bx, acc[i][j][1] + by);
                float2 v1 = make_float2(acc[i][j][2] + bx, acc[i][j][3] + by);
                *(float2*)(H + (size_t)r0 * NHID + col)       = v0;
                *(float2*)(H + (size_t)(r0 + 8) * NHID + col) = v1;
            }
        }
    }
}

// ---------------- Kernel B: warp-per-row k-winners (reverse row order for L2 reuse) ----------------
#define WPC 4
#define TB_KW (WPC * 32)
#define NV4 (NHID / 4)     // 500 packed entries (4 keys16 each)
#define CCAP 64
#define WCAP 288

__global__ __launch_bounds__(TB_KW)
void kwin_head_kernel(const float* __restrict__ H,
                      const float* __restrict__ W2t,
                      const float* __restrict__ b2v,
                      const float* __restrict__ boost,
                      float* __restrict__ out)
{
    __shared__ uint2          keysS[WPC][NV4];
    __shared__ unsigned       histS[WPC][256];
    __shared__ unsigned       candKeyS[WPC][CCAP];
    __shared__ unsigned short candIdxS[WPC][CCAP];
    __shared__ unsigned short wlistS[WPC][WCAP];

    const int lane = threadIdx.x & 31;
    const int warp = threadIdx.x >> 5;
    // reverse row order: highest rows (most recently written by gemm) first -> L2 hits
    const int row  = BATCH - 1 - (blockIdx.x * WPC + warp);
    const float*  hrow = H + (size_t)row * NHID;
    const float4* h4p  = (const float4*)hrow;
    const float4* b4p  = (const float4*)boost;
    uint2*          keys2 = keysS[warp];
    unsigned*       hist  = histS[warp];
    unsigned*       ckey  = candKeyS[warp];
    unsigned short* cidx  = candIdxS[warp];
    unsigned short* wlist = wlistS[warp];
    const unsigned FULL = 0xFFFFFFFFu;
    const unsigned laneLT = (1u << lane) - 1u;

    auto suffix_select = [&](int K, unsigned& binOut, int& kremOut) {
        unsigned gsum[8];
        #pragma unroll
        for (int g = 0; g < 8; g++) {
            unsigned s = hist[g * 32 + lane];
            #pragma unroll
            for (int off = 16; off; off >>= 1) s += __shfl_xor_sync(FULL, s, off);
            gsum[g] = s;
        }
        int gstar = 0; unsigned above = 0; unsigned run = 0;
        #pragma unroll
        for (int g = 7; g >= 0; g--) {
            if (run < (unsigned)K && run + gsum[g] >= (unsigned)K) { gstar = g; above = run; }
            run += gsum[g];
        }
        const unsigned v = hist[gstar * 32 + lane];
        unsigned suf = v;
        #pragma unroll
        for (int off = 1; off < 32; off <<= 1) {
            const unsigned t = __shfl_down_sync(FULL, suf, off);
            if (lane + off < 32) suf += t;
        }
        const unsigned suft  = suf + above;
        const unsigned below = suft - v;
        const bool found = (suft >= (unsigned)K) && (below < (unsigned)K);
        const unsigned fm = __ballot_sync(FULL, found);
        const int src = __ffs(fm) - 1;
        binOut  = (unsigned)(gstar * 32 + src);
        kremOut = __shfl_sync(FULL, (int)((unsigned)K - below), src);
    };

    #pragma unroll
    for (int g = 0; g < 8; g++) hist[g * 32 + lane] = 0u;
    __syncwarp();

    // ---- pass 1 (global): build keys16 -> smem, top-byte histogram (plain atomics) ----
    for (int v0 = 0; v0 < NV4; v0 += 32) {
        const int v = v0 + lane;
        if (v < NV4) {
            const float4 h4 = __ldg(&h4p[v]);
            const float4 b4 = __ldg(&b4p[v]);
            unsigned k16[4];
            k16[0] = key_xform(h4.x * b4.x) >> 16;
            k16[1] = key_xform(h4.y * b4.y) >> 16;
            k16[2] = key_xform(h4.z * b4.z) >> 16;
            k16[3] = key_xform(h4.w * b4.w) >> 16;
            keys2[v] = make_uint2(k16[0] | (k16[1] << 16), k16[2] | (k16[3] << 16));
            #pragma unroll
            for (int q = 0; q < 4; q++)
                atomicAdd(&hist[k16[q] >> 8], 1u);
        }
    }
    __syncwarp();

    unsigned b1; int k1;
    suffix_select(KWIN, b1, k1);

    #pragma unroll
    for (int g = 0; g < 8; g++) hist[g * 32 + lane] = 0u;
    __syncwarp();

    // ---- pass 2 (smem): low-byte histogram among top-byte == b1 ----
    for (int v0 = 0; v0 < NV4; v0 += 32) {
        const int v = v0 + lane;
        if (v < NV4) {
            const uint2 kk = keys2[v];
            const unsigned k16[4] = {kk.x & 0xFFFFu, kk.x >> 16, kk.y & 0xFFFFu, kk.y >> 16};
            #pragma unroll
            for (int q = 0; q < 4; q++)
                if ((k16[q] >> 8) == b1) atomicAdd(&hist[k16[q] & 255u], 1u);
        }
    }
    __syncwarp();

    unsigned b2bin; int k2;
    suffix_select(k1, b2bin, k2);
    const unsigned thr16 = (b1 << 8) | b2bin;

    // ---- pass 3 (smem): packed-scan compaction of strict winners + boundary candidates ----
    int wcnt = 0, ccnt = 0;
    for (int v0 = 0; v0 < NV4; v0 += 32) {
        const int v = v0 + lane;
        const bool in = v < NV4;
        unsigned k16[4]; bool sw[4], cq[4];
        unsigned nw = 0, nc = 0;
        if (in) {
            const uint2 kk = keys2[v];
            k16[0] = kk.x & 0xFFFFu; k16[1] = kk.x >> 16;
            k16[2] = kk.y & 0xFFFFu; k16[3] = kk.y >> 16;
            #pragma unroll
            for (int q = 0; q < 4; q++) {
                sw[q] = (k16[q] > thr16);
                cq[q] = (k16[q] == thr16);
                nw += sw[q]; nc += cq[q];
            }
        } else {
            #pragma unroll
            for (int q = 0; q < 4; q++) { sw[q] = false; cq[q] = false; }
        }
        unsigned pk = (nc << 16) | nw;
        unsigned sc = pk;
        #pragma unroll
        for (int off = 1; off < 32; off <<= 1) {
            const unsigned t = __shfl_up_sync(FULL, sc, off);
            if (lane >= off) sc += t;
        }
        const unsigned tot = __shfl_sync(FULL, sc, 31);
        const unsigned exc = sc - pk;
        int wpos = wcnt + (int)(exc & 0xFFFFu);
        int cpos = ccnt + (int)(exc >> 16);
        if (in) {
            #pragma unroll
            for (int q = 0; q < 4; q++) {
                if (sw[q]) {
                    if (wpos < WCAP) wlist[wpos] = (unsigned short)(v * 4 + q);
                    wpos++;
                }
                if (cq[q]) {
                    if (cpos < CCAP) cidx[cpos] = (unsigned short)(v * 4 + q);
                    cpos++;
                }
            }
        }
        wcnt += (int)(tot & 0xFFFFu);
        ccnt += (int)(tot >> 16);
    }
    __syncwarp();
    const int L = (ccnt < CCAP) ? ccnt : CCAP;
    int Wn = (wcnt < WCAP) ? wcnt : WCAP;

    // boundary candidates: full keys, exact rank (key desc, idx asc), append winners
    for (int j = lane; j < L; j += 32) {
        const int ii = cidx[j];
        ckey[j] = key_xform(__ldg(&hrow[ii]) * __ldg(&boost[ii]));
    }
    __syncwarp();
    for (int j0 = 0; j0 < L; j0 += 32) {
        const int j = j0 + lane;
        bool win = false;
        int ii = 0;
        if (j < L) {
            const unsigned ku = ckey[j];
            ii = cidx[j];
            int rank = 0;
            for (int t = 0; t < L; t++) {
                const unsigned kt = ckey[t];
                rank += (kt > ku) || (kt == ku && (int)cidx[t] < ii);
            }
            win = (rank < k2);
        }
        const unsigned mask = __ballot_sync(FULL, win);
        if (win) {
            const int pos = Wn + __popc(mask & laneLT);
            if (pos < WCAP) wlist[pos] = (unsigned short)ii;
        }
        Wn += __popc(mask);
    }
    __syncwarp();
    if (Wn > WCAP) Wn = WCAP;

    // ---- pass 4: dense accumulation over compacted winner list ----
    float acc[NCLS];
    #pragma unroll
    for (int c = 0; c < NCLS; c++) acc[c] = 0.f;

    for (int j = lane; j < Wn; j += 32) {
        const int i = wlist[j];
        const float hv = __ldg(&hrow[i]);
        const float4* wp = (const float4*)(W2t + (size_t)i * 12);
        const float4 w0 = __ldg(wp);
        const float4 w1 = __ldg(wp + 1);
        const float4 w2 = __ldg(wp + 2);
        acc[0] = fmaf(hv, w0.x, acc[0]);
        acc[1] = fmaf(hv, w0.y, acc[1]);
        acc[2] = fmaf(hv, w0.z, acc[2]);
        acc[3] = fmaf(hv, w0.w, acc[3]);
        acc[4] = fmaf(hv, w1.x, acc[4]);
        acc[5] = fmaf(hv, w1.y, acc[5]);
        acc[6] = fmaf(hv, w1.z, acc[6]);
        acc[7] = fmaf(hv, w1.w, acc[7]);
        acc[8] = fmaf(hv, w2.x, acc[8]);
        acc[9] = fmaf(hv, w2.y, acc[9]);
    }

    #pragma unroll
    for (int off = 16; off; off >>= 1)
        #pragma unroll
        for (int c = 0; c < NCLS; c++)
            acc[c] += __shfl_xor_sync(FULL, acc[c], off);

    if (lane == 0) {
        float lg[NCLS];
        #pragma unroll
        for (int c = 0; c < NCLS; c++) lg[c] = acc[c] + __ldg(&b2v[c]);
        float mx = lg[0];
        #pragma unroll
        for (int c = 1; c < NCLS; c++) mx = fmaxf(mx, lg[c]);
        float se = 0.f;
        #pragma unroll
        for (int c = 0; c < NCLS; c++) se += expf(lg[c] - mx);
        const float lse = mx + logf(se);
        float* orow = out + (size_t)row * NCLS;
        #pragma unroll
        for (int c = 0; c < NCLS; c++) orow[c] = lg[c] - lse;
    }
}

// ---------------- launch ----------------
extern "C" void kernel_launch(void* const* d_in, const int* in_sizes, int n_in,
                              void* d_out, int out_size)
{
    const float* x    = (const float*)d_in[0];   // [16384, 784]
    const float* W1   = (const float*)d_in[1];   // [2000, 784]
    const float* b1   = (const float*)d_in[2];   // [2000]
    const float* W2   = (const float*)d_in[3];   // [10, 2000]
    const float* b2   = (const float*)d_in[4];   // [10]
    const float* duty = (const float*)d_in[5];   // [2000]
    float* out = (float*)d_out;                  // [16384, 10]

    float*  h;    cudaGetSymbolAddress((void**)&h,   g_h);
    __half* xhi;  cudaGetSymbolAddress((void**)&xhi, g_xhi);
    __half* xlo;  cudaGetSymbolAddress((void**)&xlo, g_xlo);
    __half* whi;  cudaGetSymbolAddress((void**)&whi, g_whi);
    __half* wlo;  cudaGetSymbolAddress((void**)&wlo, g_wlo);
    float*  w2t;  cudaGetSymbolAddress((void**)&w2t, g_w2t);
    float*  bst;  cudaGetSymbolAddress((void**)&bst, g_boost);

    prep_kernel<<<1184, 256>>>(x, W1, W2, duty, xhi, xlo, whi, wlo, w2t, bst);

    cudaFuncSetAttribute(gemm1_mma, cudaFuncAttributeMaxDynamicSharedMemorySize, SMEM_GEMM);
    dim3 gridG((NHID + BN - 1) / BN, BATCH / BM);   // (16, 128)
    gemm1_mma<<<gridG, 256, SMEM_GEMM>>>(xhi, xlo, whi, wlo, b1, h);

    kwin_head_kernel<<<BATCH / WPC, TB_KW>>>(h, w2t, b2, bst, out);
}